// round 14
// baseline (speedup 1.0000x reference)
#include <cuda_runtime.h>
#include <cuda_bf16.h>
#include <cstdint>
#include <math.h>

#define D_MODEL 1024
#define BATCH   2
#define TQ      2048
#define SKV     4096
#define NHEADS  16
#define HDIM    64

// ---------------- scratch (no cudaMalloc allowed) ----------------
__device__ __align__(256) __nv_bfloat16 g_qh[(size_t)BATCH * TQ  * D_MODEL];
__device__ __align__(256) __nv_bfloat16 g_ql[(size_t)BATCH * TQ  * D_MODEL];
__device__ __align__(256) __nv_bfloat16 g_kvh[(size_t)BATCH * SKV * D_MODEL];
__device__ __align__(256) __nv_bfloat16 g_kvl[(size_t)BATCH * SKV * D_MODEL];
__device__ __align__(256) __nv_bfloat16 g_yh[(size_t)BATCH * TQ  * D_MODEL];
__device__ __align__(256) __nv_bfloat16 g_yl[(size_t)BATCH * TQ  * D_MODEL];
__device__ __align__(256) __nv_bfloat16 g_wh[4][(size_t)D_MODEL * D_MODEL];
__device__ __align__(256) __nv_bfloat16 g_wl[4][(size_t)D_MODEL * D_MODEL];
__device__ __align__(256) __nv_bfloat16 g_kfh[(size_t)BATCH * SKV * D_MODEL];
__device__ __align__(256) __nv_bfloat16 g_kfl[(size_t)BATCH * SKV * D_MODEL];
__device__ __align__(256) __nv_bfloat16 g_vth[(size_t)BATCH * NHEADS * HDIM * SKV];
__device__ __align__(256) __nv_bfloat16 g_vtl[(size_t)BATCH * NHEADS * HDIM * SKV];

// ---------------- primitives ----------------
__device__ __forceinline__ uint32_t smem_u32(const void* p) {
  uint32_t a;
  asm("{ .reg .u64 t; cvta.to.shared.u64 t, %1; cvt.u32.u64 %0, t; }"
      : "=r"(a) : "l"(p));
  return a;
}
__device__ __forceinline__ void ldsm4(uint32_t* r, uint32_t a) {
  asm volatile("ldmatrix.sync.aligned.m8n8.x4.shared.b16 {%0,%1,%2,%3}, [%4];"
               : "=r"(r[0]), "=r"(r[1]), "=r"(r[2]), "=r"(r[3]) : "r"(a));
}
__device__ __forceinline__ void mma16816(float* d, const uint32_t* a,
                                         const uint32_t* b) {
  asm volatile(
      "mma.sync.aligned.m16n8k16.row.col.f32.bf16.bf16.f32 "
      "{%0,%1,%2,%3}, {%4,%5,%6,%7}, {%8,%9}, {%0,%1,%2,%3};"
      : "+f"(d[0]), "+f"(d[1]), "+f"(d[2]), "+f"(d[3])
      : "r"(a[0]), "r"(a[1]), "r"(a[2]), "r"(a[3]), "r"(b[0]), "r"(b[1]));
}
__device__ __forceinline__ void cp16(uint32_t dst, const void* src) {
  asm volatile("cp.async.cg.shared.global [%0], [%1], 16;" :: "r"(dst), "l"(src));
}
#define CP_COMMIT() asm volatile("cp.async.commit_group;")

__device__ __forceinline__ void bulk_g2s(uint32_t dst, const void* src,
                                         uint32_t bytes, uint32_t mbar) {
  asm volatile(
      "cp.async.bulk.shared::cluster.global.mbarrier::complete_tx::bytes "
      "[%0], [%1], %2, [%3];"
      :: "r"(dst), "l"(src), "r"(bytes), "r"(mbar) : "memory");
}
#define MBARRIER_INIT(mbar, count)                                            \
  asm volatile("mbarrier.init.shared.b64 [%0], %1;"                           \
               :: "r"((uint32_t)(mbar)), "r"((uint32_t)(count)) : "memory")
#define MBARRIER_EXPECT_TX(mbar, tx)                                          \
  asm volatile("mbarrier.arrive.expect_tx.shared.b64 _, [%0], %1;"            \
               :: "r"((uint32_t)(mbar)), "r"((uint32_t)(tx)) : "memory")
#define MBARRIER_ARRIVE(mbar)                                                 \
  asm volatile("mbarrier.arrive.shared.b64 _, [%0];"                          \
               :: "r"((uint32_t)(mbar)) : "memory")
#define MBARRIER_WAIT_PARITY(mbar_addr, phase_parity) do {                    \
  uint32_t _mbar = (uint32_t)(mbar_addr);                                     \
  uint32_t _par = (uint32_t)(phase_parity);                                   \
  uint32_t _done;                                                             \
  asm volatile(                                                               \
      "{\n\t.reg .pred p;\n\t"                                                \
      "mbarrier.try_wait.parity.acquire.cta.shared::cta.b64 p, [%1], %2;\n\t" \
      "selp.b32 %0, 1, 0, p;\n\t}"                                            \
      : "=r"(_done) : "r"(_mbar), "r"(_par) : "memory");                      \
  if (!_done) {                                                               \
    asm volatile(                                                             \
        "{\n\t.reg .pred P1;\n\t"                                             \
        "WAIT_LOOP_%=:\n\t"                                                   \
        "mbarrier.try_wait.parity.acquire.cta.shared::cta.b64 P1, [%0], %1, 0x989680;\n\t" \
        "@P1 bra.uni WAIT_DONE_%=;\n\t"                                       \
        "bra.uni WAIT_LOOP_%=;\n\t"                                           \
        "WAIT_DONE_%=:\n\t}"                                                  \
        :: "r"(_mbar), "r"(_par) : "memory");                                 \
  }                                                                           \
} while (0)

__device__ __forceinline__ void pack_hilo(float p0, float p1, uint32_t& hi,
                                          uint32_t& lo) {
  __nv_bfloat162 h = __floats2bfloat162_rn(p0, p1);
  float r0 = p0 - __bfloat162float(h.x);
  float r1 = p1 - __bfloat162float(h.y);
  __nv_bfloat162 l = __floats2bfloat162_rn(r0, r1);
  hi = *reinterpret_cast<uint32_t*>(&h);
  lo = *reinterpret_cast<uint32_t*>(&l);
}

// ---------------------------------------------------------------------------
// Fused pack with 4-way MLP: thread id handles 4 independent groups, one per
// compile-time region (query[id], kv[id], kv[id+STRIDE], weights[id]).
// GEMM tile layout: [mb][kc][128x32 halves], 64B rows, seg^=((r>>1)&3).
// ---------------------------------------------------------------------------
#define NQ8  (BATCH * TQ * D_MODEL / 8)    // 524288
#define NKV8 (BATCH * SKV * D_MODEL / 8)   // 1048576
#define NW8  (D_MODEL * D_MODEL / 8)       // 131072
#define PSTRIDE 524288

__device__ __forceinline__ void pack_group(const float* __restrict__ src,
                                           __nv_bfloat16* __restrict__ dh,
                                           __nv_bfloat16* __restrict__ dl,
                                           size_t base, int e) {
  float4 a = *(const float4*)src;
  float4 b = *(const float4*)(src + 4);
  uint32_t h0, h1, h2, h3, l0, l1, l2, l3;
  pack_hilo(a.x, a.y, h0, l0);
  pack_hilo(a.z, a.w, h1, l1);
  pack_hilo(b.x, b.y, h2, l2);
  pack_hilo(b.z, b.w, h3, l3);
  int m = e >> 10, k = e & 1023;
  int r = m & 127, mb = m >> 7, kc = k >> 5, seg = (k >> 3) & 3;
  size_t t = base + ((size_t)mb * 32 + kc) * 4096 + r * 32 +
             ((seg ^ ((r >> 1) & 3)) << 3);
  *(uint4*)(dh + t) = make_uint4(h0, h1, h2, h3);
  *(uint4*)(dl + t) = make_uint4(l0, l1, l2, l3);
}

__global__ void pack_all4(const float* __restrict__ query,
                          const float* __restrict__ key_value,
                          const float* __restrict__ w0,
                          const float* __restrict__ w1,
                          const float* __restrict__ w2,
                          const float* __restrict__ w3,
                          __nv_bfloat16* __restrict__ qh,
                          __nv_bfloat16* __restrict__ ql,
                          __nv_bfloat16* __restrict__ kvh,
                          __nv_bfloat16* __restrict__ kvl,
                          __nv_bfloat16* __restrict__ wph,
                          __nv_bfloat16* __restrict__ wpl) {
  int id = blockIdx.x * blockDim.x + threadIdx.x;   // 0 .. PSTRIDE-1
  // Four independent source loads (issued back-to-back -> MLP=4).
  const float* s0 = query + (size_t)id * 8;                       // query
  const float* s1 = key_value + (size_t)id * 8;                   // kv half 0
  const float* s2 = key_value + ((size_t)id + PSTRIDE) * 8;       // kv half 1
  int w = id >> 17, wi = id & (NW8 - 1);                          // weights
  const float* s3 = (w == 0 ? w0 : w == 1 ? w1 : w == 2 ? w2 : w3) +
                    (size_t)wi * 8;
  float4 a0 = *(const float4*)s0, b0 = *(const float4*)(s0 + 4);
  float4 a1 = *(const float4*)s1, b1 = *(const float4*)(s1 + 4);
  float4 a2 = *(const float4*)s2, b2 = *(const float4*)(s2 + 4);
  float4 a3 = *(const float4*)s3, b3 = *(const float4*)(s3 + 4);

  // Convert + store each group (same arithmetic as before, per element).
  {
    const float4 av[2] = {a0, b0};
    uint32_t h0, h1, h2, h3, l0, l1, l2, l3;
    pack_hilo(av[0].x, av[0].y, h0, l0);
    pack_hilo(av[0].z, av[0].w, h1, l1);
    pack_hilo(av[1].x, av[1].y, h2, l2);
    pack_hilo(av[1].z, av[1].w, h3, l3);
    int e = id * 8;
    int m = e >> 10, k = e & 1023;
    int r = m & 127, mb = m >> 7, kc = k >> 5, seg = (k >> 3) & 3;
    size_t t = ((size_t)mb * 32 + kc) * 4096 + r * 32 +
               ((seg ^ ((r >> 1) & 3)) << 3);
    *(uint4*)(qh + t) = make_uint4(h0, h1, h2, h3);
    *(uint4*)(ql + t) = make_uint4(l0, l1, l2, l3);
  }
  {
    const float4 av[2] = {a1, b1};
    uint32_t h0, h1, h2, h3, l0, l1, l2, l3;
    pack_hilo(av[0].x, av[0].y, h0, l0);
    pack_hilo(av[0].z, av[0].w, h1, l1);
    pack_hilo(av[1].x, av[1].y, h2, l2);
    pack_hilo(av[1].z, av[1].w, h3, l3);
    int e = id * 8;
    int m = e >> 10, k = e & 1023;
    int r = m & 127, mb = m >> 7, kc = k >> 5, seg = (k >> 3) & 3;
    size_t t = ((size_t)mb * 32 + kc) * 4096 + r * 32 +
               ((seg ^ ((r >> 1) & 3)) << 3);
    *(uint4*)(kvh + t) = make_uint4(h0, h1, h2, h3);
    *(uint4*)(kvl + t) = make_uint4(l0, l1, l2, l3);
  }
  {
    const float4 av[2] = {a2, b2};
    uint32_t h0, h1, h2, h3, l0, l1, l2, l3;
    pack_hilo(av[0].x, av[0].y, h0, l0);
    pack_hilo(av[0].z, av[0].w, h1, l1);
    pack_hilo(av[1].x, av[1].y, h2, l2);
    pack_hilo(av[1].z, av[1].w, h3, l3);
    int e = (id + PSTRIDE) * 8;
    int m = e >> 10, k = e & 1023;
    int r = m & 127, mb = m >> 7, kc = k >> 5, seg = (k >> 3) & 3;
    size_t t = ((size_t)mb * 32 + kc) * 4096 + r * 32 +
               ((seg ^ ((r >> 1) & 3)) << 3);
    *(uint4*)(kvh + t) = make_uint4(h0, h1, h2, h3);
    *(uint4*)(kvl + t) = make_uint4(l0, l1, l2, l3);
  }
  {
    const float4 av[2] = {a3, b3};
    uint32_t h0, h1, h2, h3, l0, l1, l2, l3;
    pack_hilo(av[0].x, av[0].y, h0, l0);
    pack_hilo(av[0].z, av[0].w, h1, l1);
    pack_hilo(av[1].x, av[1].y, h2, l2);
    pack_hilo(av[1].z, av[1].w, h3, l3);
    int e = wi * 8;
    int m = e >> 10, k = e & 1023;
    int r = m & 127, mb = m >> 7, kc = k >> 5, seg = (k >> 3) & 3;
    size_t t = (size_t)w * D_MODEL * D_MODEL +
               ((size_t)mb * 32 + kc) * 4096 + r * 32 +
               ((seg ^ ((r >> 1) & 3)) << 3);
    *(uint4*)(wph + t) = make_uint4(h0, h1, h2, h3);
    *(uint4*)(wpl + t) = make_uint4(l0, l1, l2, l3);
  }
}

// ---------------------------------------------------------------------------
// GEMM core: bf16x3 NT, 3-stage bulk-DMA pipeline, full/empty mbarriers.
// Round-9 proven mma order (same-acc chains are free on this part).
// ---------------------------------------------------------------------------
#define NCH      32
#define GS_TILE  8192
#define GS_STAGE 32768
#define GS_FULL  98304
#define GS_EMPTY 98328
#define GS_SMEM  98432

__device__ __forceinline__ void gemm_mainloop(
    const __nv_bfloat16* Ah, const __nv_bfloat16* Al,
    const __nv_bfloat16* Bh, const __nv_bfloat16* Bl,
    int mb, int nb, uint32_t sb, int tid, int lane, int warp,
    float acc[2][8][4]) {
  const int wm = (warp & 3) * 32;
  const int wn = (warp >> 2) * 64;

  if (tid == 0) {
#pragma unroll
    for (int s = 0; s < 3; s++) {
      MBARRIER_INIT(sb + GS_FULL + s * 8, 1);
      MBARRIER_INIT(sb + GS_EMPTY + s * 8, 8);
    }
  }
  __syncthreads();

#define G_BULK(c_, s_) do {                                                   \
    uint32_t fb_ = sb + GS_FULL + (s_) * 8;                                   \
    MBARRIER_EXPECT_TX(fb_, 32768u);                                          \
    uint32_t d_ = sb + (uint32_t)(s_) * GS_STAGE;                             \
    bulk_g2s(d_,             Ah + ((size_t)(mb * NCH + (c_))) * 4096, 8192u, fb_); \
    bulk_g2s(d_ + GS_TILE,   Al + ((size_t)(mb * NCH + (c_))) * 4096, 8192u, fb_); \
    bulk_g2s(d_ + 2*GS_TILE, Bh + ((size_t)(nb * NCH + (c_))) * 4096, 8192u, fb_); \
    bulk_g2s(d_ + 3*GS_TILE, Bl + ((size_t)(nb * NCH + (c_))) * 4096, 8192u, fb_); \
  } while (0)

  if (tid == 0) {
    G_BULK(0, 0);
    G_BULK(1, 1);
  }

  const int ar = lane & 15;
  const int ac = ((lane >> 4) & 1) * 8;
  const int nof = ((lane >> 4) & 1) * 8 + (lane & 7);
  const int kof2 = ((lane >> 3) & 1) * 8;

  for (int c = 0; c < NCH; c++) {
    const int cur = c % 3;
    const int cp = c + 2;
    if (cp < NCH && tid == 0) {
      const int sp = cp % 3;
      if (cp >= 3)
        MBARRIER_WAIT_PARITY(sb + GS_EMPTY + sp * 8, ((cp / 3) - 1) & 1);
      G_BULK(cp, sp);
    }
    MBARRIER_WAIT_PARITY(sb + GS_FULL + cur * 8, (c / 3) & 1);

    const uint32_t st = sb + (uint32_t)cur * GS_STAGE;
#pragma unroll
    for (int ks = 0; ks < 2; ks++) {
      const int k0 = ks * 16;
      uint32_t afh[2][4], afl[2][4];
#pragma unroll
      for (int mi = 0; mi < 2; mi++) {
        int r = wm + mi * 16 + ar;
        int seg = (k0 + ac) >> 3;
        uint32_t ad = st + (uint32_t)(r * 64 + ((seg ^ ((r >> 1) & 3)) << 4));
        ldsm4(afh[mi], ad);
        ldsm4(afl[mi], ad + GS_TILE);
      }
#pragma unroll
      for (int ni = 0; ni < 4; ni++) {
        int rb = wn + ni * 16 + nof;
        int segb = (k0 + kof2) >> 3;
        uint32_t bd = st + 2 * GS_TILE +
                      (uint32_t)(rb * 64 + ((segb ^ ((rb >> 1) & 3)) << 4));
        uint32_t bh[4], bl[4];
        ldsm4(bh, bd);
        ldsm4(bl, bd + GS_TILE);
#pragma unroll
        for (int mi = 0; mi < 2; mi++)
#pragma unroll
          for (int hh = 0; hh < 2; hh++) {
            int nj = ni * 2 + hh;
            mma16816(acc[mi][nj], afh[mi], &bh[2 * hh]);
            mma16816(acc[mi][nj], afh[mi], &bl[2 * hh]);
            mma16816(acc[mi][nj], afl[mi], &bh[2 * hh]);
          }
      }
    }
    if (lane == 0) MBARRIER_ARRIVE(sb + GS_EMPTY + cur * 8);
  }
#undef G_BULK
}

// ---------------------------------------------------------------------------
// Fused Q/K/V projection: 1280 CTAs, runtime mode decode.
// ---------------------------------------------------------------------------
__global__ __launch_bounds__(256, 2)
void proj_fused(const __nv_bfloat16* __restrict__ qh,
                const __nv_bfloat16* __restrict__ ql,
                const __nv_bfloat16* __restrict__ kvh,
                const __nv_bfloat16* __restrict__ kvl,
                const __nv_bfloat16* __restrict__ wph,
                const __nv_bfloat16* __restrict__ wpl,
                __nv_bfloat16* __restrict__ yh,
                __nv_bfloat16* __restrict__ yl,
                __nv_bfloat16* __restrict__ kfh,
                __nv_bfloat16* __restrict__ kfl,
                __nv_bfloat16* __restrict__ vth,
                __nv_bfloat16* __restrict__ vtl) {
  extern __shared__ __align__(128) char sm[];
  const uint32_t sb = smem_u32(sm);
  const int tid = threadIdx.x, lane = tid & 31, warp = tid >> 5;
  const size_t WSZ = (size_t)D_MODEL * D_MODEL;

  int id = blockIdx.x;
  int mode, bx, by;
  const __nv_bfloat16 *Ah, *Al, *Bh, *Bl;
  __nv_bfloat16 *Ph, *Pl;
  if (id < 256) {
    mode = 1; bx = id & 7; by = id >> 3;
    Ah = qh; Al = ql; Bh = wph; Bl = wpl; Ph = yh; Pl = yl;
  } else if (id < 768) {
    mode = 2; id -= 256; bx = id & 7; by = id >> 3;
    Ah = kvh; Al = kvl; Bh = wph + WSZ; Bl = wpl + WSZ; Ph = kfh; Pl = kfl;
  } else {
    mode = 3; id -= 768; bx = id & 63; by = id >> 6;
    Ah = wph + 2 * WSZ; Al = wpl + 2 * WSZ; Bh = kvh; Bl = kvl;
    Ph = vth; Pl = vtl;
  }
  const int bm = by * 128, bn = bx * 128;

  float acc[2][8][4];
#pragma unroll
  for (int mi = 0; mi < 2; mi++)
#pragma unroll
    for (int nj = 0; nj < 8; nj++)
#pragma unroll
      for (int q = 0; q < 4; q++) acc[mi][nj][q] = 0.0f;

  gemm_mainloop(Ah, Al, Bh, Bl, by, bx, sb, tid, lane, warp, acc);

  const int wm = (warp & 3) * 32;
  const int wn = (warp >> 2) * 64;
  const int crow = lane >> 2;
  const int ccol = (lane & 3) * 2;
#pragma unroll
  for (int mi = 0; mi < 2; mi++)
#pragma unroll
    for (int nj = 0; nj < 8; nj++) {
      int m0 = bm + wm + mi * 16 + crow;
      int cc = bn + wn + nj * 8 + ccol;
#pragma unroll
      for (int half = 0; half < 2; half++) {
        int m = m0 + half * 8;
        float v0 = acc[mi][nj][half * 2], v1 = acc[mi][nj][half * 2 + 1];
        size_t t;
        if (mode == 1) {
          int b = m >> 11, q = m & 2047;
          int h = cc >> 6, dd = cc & 63;
          t = ((size_t)(b * 16 + h) * 16 + (q >> 7)) * 8192 +
              (size_t)(q & 127) * 64 + (((dd >> 3) ^ (q & 7)) << 3) + (dd & 7);
        } else if (mode == 2) {
          int b = m >> 12, s = m & 4095;
          int h = cc >> 6, dd = cc & 63;
          t = ((size_t)(b * 16 + h) * 64 + (s >> 6)) * 4096 +
              (size_t)(s & 63) * 64 + (((dd >> 3) ^ (s & 7)) << 3) + (dd & 7);
        } else {
          int h = m >> 6, dr = m & 63;
          int b = cc >> 12, s = cc & 4095;
          t = ((size_t)(b * 16 + h) * 64 + (s >> 6)) * 4096 +
              (size_t)dr * 64 + ((((s >> 3) & 7) ^ (dr & 7)) << 3) + (s & 7);
        }
        uint32_t hi, lo;
        pack_hilo(v0, v1, hi, lo);
        *(uint32_t*)(Ph + t) = hi;
        *(uint32_t*)(Pl + t) = lo;
      }
    }
}

// ---------------------------------------------------------------------------
// Output projection: fp32 C row-major (straight into d_out).
// ---------------------------------------------------------------------------
__global__ __launch_bounds__(256, 2)
void gemm_out(const __nv_bfloat16* __restrict__ Ah,
              const __nv_bfloat16* __restrict__ Al,
              const __nv_bfloat16* __restrict__ Bh,
              const __nv_bfloat16* __restrict__ Bl,
              float* __restrict__ C, int N) {
  extern __shared__ __align__(128) char sm[];
  const uint32_t sb = smem_u32(sm);
  const int tid = threadIdx.x, lane = tid & 31, warp = tid >> 5;
  const int bm = blockIdx.y * 128;
  const int bn = blockIdx.x * 128;

  float acc[2][8][4];
#pragma unroll
  for (int mi = 0; mi < 2; mi++)
#pragma unroll
    for (int nj = 0; nj < 8; nj++)
#pragma unroll
      for (int q = 0; q < 4; q++) acc[mi][nj][q] = 0.0f;

  gemm_mainloop(Ah, Al, Bh, Bl, blockIdx.y, blockIdx.x, sb, tid, lane, warp, acc);

  const int wm = (warp & 3) * 32;
  const int wn = (warp >> 2) * 64;
  const int crow = lane >> 2;
  const int ccol = (lane & 3) * 2;
#pragma unroll
  for (int mi = 0; mi < 2; mi++)
#pragma unroll
    for (int nj = 0; nj < 8; nj++) {
      int r0 = bm + wm + mi * 16 + crow;
      int cc = bn + wn + nj * 8 + ccol;
      *(float2*)(C + (size_t)r0 * N + cc) =
          make_float2(acc[mi][nj][0], acc[mi][nj][1]);
      *(float2*)(C + (size_t)(r0 + 8) * N + cc) =
          make_float2(acc[mi][nj][2], acc[mi][nj][3]);
    }
}

// ---------------------------------------------------------------------------
// HMMA flash attention: round-9 schedule at 2 CTAs/SM (round-13 proven).
// ---------------------------------------------------------------------------
#define FS_TILE  8192
#define FS_STAGE 32768
#define FS_QOFF  65536
#define FS_FULL  98304
#define FS_EMPTY 98328
#define FS_SMEM  98432

__global__ __launch_bounds__(256, 2)
void flash_bulk(const __nv_bfloat16* __restrict__ qfh,
                const __nv_bfloat16* __restrict__ qfl,
                const __nv_bfloat16* __restrict__ kfh,
                const __nv_bfloat16* __restrict__ kfl,
                const __nv_bfloat16* __restrict__ vth,
                const __nv_bfloat16* __restrict__ vtl,
                const float* __restrict__ imp,
                __nv_bfloat16* __restrict__ Yh,
                __nv_bfloat16* __restrict__ Yl) {
  extern __shared__ __align__(128) char fsm[];
  const uint32_t sb = smem_u32(fsm);
  const int b = blockIdx.z, h = blockIdx.y, qb = blockIdx.x;
  const int q0 = qb * 128;
  const int tid = threadIdx.x, lane = tid & 31, warp = tid >> 5;
  const int wm = warp * 16;

  if (tid == 0) {
#pragma unroll
    for (int s = 0; s < 3; s++) {
      MBARRIER_INIT(sb + FS_FULL + s * 8, 1);
      MBARRIER_INIT(sb + FS_EMPTY + s * 8, 8);
    }
  }
  {
    const __nv_bfloat16* qsrc = qfh + ((size_t)(b * 16 + h) * 16 + qb) * 8192;
    const __nv_bfloat16* qsrc2 = qfl + ((size_t)(b * 16 + h) * 16 + qb) * 8192;
#pragma unroll
    for (int j = 0; j < 4; j++) {
      int idx = tid + j * 256;
      cp16(sb + FS_QOFF + idx * 16, qsrc + idx * 8);
      cp16(sb + FS_QOFF + 16384 + idx * 16, qsrc2 + idx * 8);
    }
  }
  CP_COMMIT();
  __syncthreads();

  const __nv_bfloat16* Kb = kfh + ((size_t)(b * 16 + h) * 64) * 4096;
  const __nv_bfloat16* Kb2 = kfl + ((size_t)(b * 16 + h) * 64) * 4096;
  const __nv_bfloat16* Vb = vth + ((size_t)(b * 16 + h) * 64) * 4096;
  const __nv_bfloat16* Vb2 = vtl + ((size_t)(b * 16 + h) * 64) * 4096;

#define F_BULK(t_, s_) do {                                                   \
    uint32_t fb_ = sb + FS_FULL + (s_) * 8;                                   \
    MBARRIER_EXPECT_TX(fb_, 32768u);                                          \
    uint32_t d_ = sb + (uint32_t)(s_) * FS_STAGE;                             \
    bulk_g2s(d_,             Kb  + (size_t)(t_) * 4096, 8192u, fb_);          \
    bulk_g2s(d_ + FS_TILE,   Kb2 + (size_t)(t_) * 4096, 8192u, fb_);          \
    bulk_g2s(d_ + 2*FS_TILE, Vb  + (size_t)(t_) * 4096, 8192u, fb_);          \
    bulk_g2s(d_ + 3*FS_TILE, Vb2 + (size_t)(t_) * 4096, 8192u, fb_);          \
  } while (0)

  if (tid == 0) {
    F_BULK(0, 0);
    F_BULK(1, 1);
  }

  const int ar = lane & 15;
  const int ac = ((lane >> 4) & 1) * 8;
  const int nof = ((lane >> 4) & 1) * 8 + (lane & 7);
  const int kof2 = ((lane >> 3) & 1) * 8;

  asm volatile("cp.async.wait_group 0;");
  __syncthreads();
  uint32_t qfa[4][4], qfb[4][4];
#pragma unroll
  for (int kc = 0; kc < 4; kc++) {
    int r = wm + ar;
    int seg = 2 * kc + (ac >> 3);
    uint32_t ad = sb + FS_QOFF + (uint32_t)(r * 128 + ((seg ^ (r & 7)) << 4));
    ldsm4(qfa[kc], ad);
    ldsm4(qfb[kc], ad + 16384);
  }
  __syncthreads();

  const int q2 = (lane & 3) * 2;
  float lg[4];
  lg[0] = logf(fmaxf(imp[b * NHEADS + (q2 & 15)], 1e-6f));
  lg[1] = logf(fmaxf(imp[b * NHEADS + ((q2 + 1) & 15)], 1e-6f));
  lg[2] = logf(fmaxf(imp[b * NHEADS + ((q2 + 8) & 15)], 1e-6f));
  lg[3] = logf(fmaxf(imp[b * NHEADS + ((q2 + 9) & 15)], 1e-6f));

  float m0 = -INFINITY, m1 = -INFINITY, l0 = 0.0f, l1 = 0.0f;
  float y[8][4];
#pragma unroll
  for (int nf = 0; nf < 8; nf++)
#pragma unroll
    for (int q = 0; q < 4; q++) y[nf][q] = 0.0f;

  const int NT = SKV / 64;
  for (int t = 0; t < NT; t++) {
    const int cur = t % 3;
    const int cp = t + 2;
    if (cp < NT && tid == 0) {
      const int sp = cp % 3;
      if (cp >= 3)
        MBARRIER_WAIT_PARITY(sb + FS_EMPTY + sp * 8, ((cp / 3) - 1) & 1);
      F_BULK(cp, sp);
    }
    MBARRIER_WAIT_PARITY(sb + FS_FULL + cur * 8, (t / 3) & 1);
    const uint32_t st = sb + (uint32_t)cur * FS_STAGE;

    float s[8][4];
#pragma unroll
    for (int nf = 0; nf < 8; nf++)
#pragma unroll
      for (int q = 0; q < 4; q++) s[nf][q] = 0.0f;
#pragma unroll
    for (int kc = 0; kc < 4; kc++) {
#pragma unroll
      for (int n2 = 0; n2 < 4; n2++) {
        int r = n2 * 16 + nof;
        int seg = 2 * kc + (kof2 >> 3);
        uint32_t bd = st + (uint32_t)(r * 128 + ((seg ^ (r & 7)) << 4));
        uint32_t bh[4], bl[4];
        ldsm4(bh, bd);
        ldsm4(bl, bd + FS_TILE);
#pragma unroll
        for (int hh = 0; hh < 2; hh++) {
          mma16816(s[n2 * 2 + hh], qfa[kc], &bh[2 * hh]);
          mma16816(s[n2 * 2 + hh], qfa[kc], &bl[2 * hh]);
          mma16816(s[n2 * 2 + hh], qfb[kc], &bh[2 * hh]);
        }
      }
    }

    float mt0 = -INFINITY, mt1 = -INFINITY;
#pragma unroll
    for (int nf = 0; nf < 8; nf++) {
      const int p = (nf & 1) * 2;
      s[nf][0] = s[nf][0] * 0.125f + lg[p];
      s[nf][1] = s[nf][1] * 0.125f + lg[p + 1];
      s[nf][2] = s[nf][2] * 0.125f + lg[p];
      s[nf][3] = s[nf][3] * 0.125f + lg[p + 1];
      mt0 = fmaxf(mt0, fmaxf(s[nf][0], s[nf][1]));
      mt1 = fmaxf(mt1, fmaxf(s[nf][2], s[nf][3]));
    }
    mt0 = fmaxf(mt0, __shfl_xor_sync(0xffffffffu, mt0, 1));
    mt0 = fmaxf(mt0, __shfl_xor_sync(0xffffffffu, mt0, 2));
    mt1 = fmaxf(mt1, __shfl_xor_sync(0xffffffffu, mt1, 1));
    mt1 = fmaxf(mt1, __shfl_xor_sync(0xffffffffu, mt1, 2));

    float mn0 = fmaxf(m0, mt0), mn1 = fmaxf(m1, mt1);
    float c0 = __expf(m0 - mn0), c1 = __expf(m1 - mn1);
    m0 = mn0; m1 = mn1;

    uint32_t ph[4][4], pl[4][4];
    float r0 = 0.0f, r1 = 0.0f;
#pragma unroll
    for (int nf = 0; nf < 8; nf++) {
      float p0 = __expf(s[nf][0] - m0);
      float p1 = __expf(s[nf][1] - m0);
      float p2 = __expf(s[nf][2] - m1);
      float p3 = __expf(s[nf][3] - m1);
      r0 += p0 + p1;
      r1 += p2 + p3;
      const int kc = nf >> 1, o = (nf & 1) * 2;
      pack_hilo(p0, p1, ph[kc][o], pl[kc][o]);
      pack_hilo(p2, p3, ph[kc][o + 1], pl[kc][o + 1]);
    }
    r0 += __shfl_xor_sync(0xffffffffu, r0, 1);
    r0 += __shfl_xor_sync(0xffffffffu, r0, 2);
    r1 += __shfl_xor_sync(0xffffffffu, r1, 1);
    r1 += __shfl_xor_sync(0xffffffffu, r1, 2);
    l0 = l0 * c0 + r0;
    l1 = l1 * c1 + r1;
#pragma unroll
    for (int nf = 0; nf < 8; nf++) {
      y[nf][0] *= c0; y[nf][1] *= c0;
      y[nf][2] *= c1; y[nf][3] *= c1;
    }

#pragma unroll
    for (int kc = 0; kc < 4; kc++) {
#pragma unroll
      for (int n2 = 0; n2 < 4; n2++) {
        int r = n2 * 16 + nof;
        int seg = 2 * kc + (kof2 >> 3);
        uint32_t bd = st + 2 * FS_TILE +
                      (uint32_t)(r * 128 + ((seg ^ (r & 7)) << 4));
        uint32_t vh[4], vl[4];
        ldsm4(vh, bd);
        ldsm4(vl, bd + FS_TILE);
#pragma unroll
        for (int hh = 0; hh < 2; hh++) {
          mma16816(y[n2 * 2 + hh], ph[kc], &vh[2 * hh]);
          mma16816(y[n2 * 2 + hh], ph[kc], &vl[2 * hh]);
          mma16816(y[n2 * 2 + hh], pl[kc], &vh[2 * hh]);
        }
      }
    }
    if (lane == 0) MBARRIER_ARRIVE(sb + FS_EMPTY + cur * 8);
  }

  const float i0 = 1.0f / l0, i1 = 1.0f / l1;
  const int row0 = q0 + wm + (lane >> 2);
#pragma unroll
  for (int nf = 0; nf < 8; nf++) {
    int k = h * HDIM + 8 * nf + q2;
    int kc = k >> 5, seg0 = (k >> 3) & 3, klow = k & 7;
#pragma unroll
    for (int half = 0; half < 2; half++) {
      int m = b * TQ + row0 + half * 8;
      float v0 = y[nf][half * 2] * (half ? i1 : i0);
      float v1 = y[nf][half * 2 + 1] * (half ? i1 : i0);
      int r = m & 127, mb2 = m >> 7;
      size_t t = ((size_t)mb2 * 32 + kc) * 4096 + (size_t)r * 32 +
                 ((seg0 ^ ((r >> 1) & 3)) << 3) + klow;
      uint32_t hi, lo;
      pack_hilo(v0, v1, hi, lo);
      *(uint32_t*)(Yh + t) = hi;
      *(uint32_t*)(Yl + t) = lo;
    }
  }
}

// ---------------------------------------------------------------------------
extern "C" void kernel_launch(void* const* d_in, const int* in_sizes, int n_in,
                              void* d_out, int out_size) {
  const float* query     = (const float*)d_in[0];
  const float* key_value = (const float*)d_in[1];
  const float* imp       = (const float*)d_in[2];
  const float* Wq        = (const float*)d_in[3];
  const float* Wk        = (const float*)d_in[4];
  const float* Wv        = (const float*)d_in[5];
  const float* Wo        = (const float*)d_in[6];
  float* out = (float*)d_out;

  __nv_bfloat16 *qh, *ql, *kvh, *kvl, *yh, *yl, *wh, *wl, *kfh, *kfl, *vth, *vtl;
  cudaGetSymbolAddress((void**)&qh, g_qh);
  cudaGetSymbolAddress((void**)&ql, g_ql);
  cudaGetSymbolAddress((void**)&kvh, g_kvh);
  cudaGetSymbolAddress((void**)&kvl, g_kvl);
  cudaGetSymbolAddress((void**)&yh, g_yh);
  cudaGetSymbolAddress((void**)&yl, g_yl);
  cudaGetSymbolAddress((void**)&wh, g_wh);
  cudaGetSymbolAddress((void**)&wl, g_wl);
  cudaGetSymbolAddress((void**)&kfh, g_kfh);
  cudaGetSymbolAddress((void**)&kfl, g_kfl);
  cudaGetSymbolAddress((void**)&vth, g_vth);
  cudaGetSymbolAddress((void**)&vtl, g_vtl);
  const size_t WSZ = (size_t)D_MODEL * D_MODEL;

  cudaFuncSetAttribute(proj_fused,
                       cudaFuncAttributeMaxDynamicSharedMemorySize, GS_SMEM);
  cudaFuncSetAttribute(gemm_out,
                       cudaFuncAttributeMaxDynamicSharedMemorySize, GS_SMEM);
  cudaFuncSetAttribute(flash_bulk,
                       cudaFuncAttributeMaxDynamicSharedMemorySize, FS_SMEM);

  // 1) Pack everything in one launch, 4 independent groups per thread.
  pack_all4<<<PSTRIDE / 256, 256>>>(query, key_value, Wq, Wk, Wv, Wo,
                                    qh, ql, kvh, kvl, wh, wl);

  // 2) Q/K/V projections fused (1280 CTAs).
  proj_fused<<<1280, 256, GS_SMEM>>>(qh, ql, kvh, kvl, wh, wl,
                                     yh, yl, kfh, kfl, vth, vtl);

  // 3) Flash attention -> Y packed as GEMM-A tiles (qh/ql reused).
  flash_bulk<<<dim3(TQ / 128, NHEADS, BATCH), 256, FS_SMEM>>>(
      yh, yl, kfh, kfl, vth, vtl, imp, qh, ql);

  // 4) Output projection -> fp32 out.
  gemm_out<<<dim3(8, 32), 256, GS_SMEM>>>(
      qh, ql, wh + 3 * WSZ, wl + 3 * WSZ, out, D_MODEL);
}

// round 16
// speedup vs baseline: 1.0134x; 1.0134x over previous
#include <cuda_runtime.h>
#include <cuda_bf16.h>
#include <cstdint>
#include <math.h>

#define D_MODEL 1024
#define BATCH   2
#define TQ      2048
#define SKV     4096
#define NHEADS  16
#define HDIM    64

// ---------------- scratch (no cudaMalloc allowed) ----------------
__device__ __align__(256) __nv_bfloat16 g_qh[(size_t)BATCH * TQ  * D_MODEL];
__device__ __align__(256) __nv_bfloat16 g_ql[(size_t)BATCH * TQ  * D_MODEL];
__device__ __align__(256) __nv_bfloat16 g_kvh[(size_t)BATCH * SKV * D_MODEL];
__device__ __align__(256) __nv_bfloat16 g_kvl[(size_t)BATCH * SKV * D_MODEL];
__device__ __align__(256) __nv_bfloat16 g_yh[(size_t)BATCH * TQ  * D_MODEL];
__device__ __align__(256) __nv_bfloat16 g_yl[(size_t)BATCH * TQ  * D_MODEL];
__device__ __align__(256) __nv_bfloat16 g_wh[4][(size_t)D_MODEL * D_MODEL];
__device__ __align__(256) __nv_bfloat16 g_wl[4][(size_t)D_MODEL * D_MODEL];
__device__ __align__(256) __nv_bfloat16 g_kfh[(size_t)BATCH * SKV * D_MODEL];
__device__ __align__(256) __nv_bfloat16 g_kfl[(size_t)BATCH * SKV * D_MODEL];
__device__ __align__(256) __nv_bfloat16 g_vth[(size_t)BATCH * NHEADS * HDIM * SKV];
__device__ __align__(256) __nv_bfloat16 g_vtl[(size_t)BATCH * NHEADS * HDIM * SKV];

// ---------------- primitives ----------------
__device__ __forceinline__ uint32_t smem_u32(const void* p) {
  uint32_t a;
  asm("{ .reg .u64 t; cvta.to.shared.u64 t, %1; cvt.u32.u64 %0, t; }"
      : "=r"(a) : "l"(p));
  return a;
}
__device__ __forceinline__ void ldsm4(uint32_t* r, uint32_t a) {
  asm volatile("ldmatrix.sync.aligned.m8n8.x4.shared.b16 {%0,%1,%2,%3}, [%4];"
               : "=r"(r[0]), "=r"(r[1]), "=r"(r[2]), "=r"(r[3]) : "r"(a));
}
__device__ __forceinline__ void mma16816(float* d, const uint32_t* a,
                                         const uint32_t* b) {
  asm volatile(
      "mma.sync.aligned.m16n8k16.row.col.f32.bf16.bf16.f32 "
      "{%0,%1,%2,%3}, {%4,%5,%6,%7}, {%8,%9}, {%0,%1,%2,%3};"
      : "+f"(d[0]), "+f"(d[1]), "+f"(d[2]), "+f"(d[3])
      : "r"(a[0]), "r"(a[1]), "r"(a[2]), "r"(a[3]), "r"(b[0]), "r"(b[1]));
}
__device__ __forceinline__ void cp16(uint32_t dst, const void* src) {
  asm volatile("cp.async.cg.shared.global [%0], [%1], 16;" :: "r"(dst), "l"(src));
}
#define CP_COMMIT() asm volatile("cp.async.commit_group;")

__device__ __forceinline__ void bulk_g2s(uint32_t dst, const void* src,
                                         uint32_t bytes, uint32_t mbar) {
  asm volatile(
      "cp.async.bulk.shared::cluster.global.mbarrier::complete_tx::bytes "
      "[%0], [%1], %2, [%3];"
      :: "r"(dst), "l"(src), "r"(bytes), "r"(mbar) : "memory");
}
#define MBARRIER_INIT(mbar, count)                                            \
  asm volatile("mbarrier.init.shared.b64 [%0], %1;"                           \
               :: "r"((uint32_t)(mbar)), "r"((uint32_t)(count)) : "memory")
#define MBARRIER_EXPECT_TX(mbar, tx)                                          \
  asm volatile("mbarrier.arrive.expect_tx.shared.b64 _, [%0], %1;"            \
               :: "r"((uint32_t)(mbar)), "r"((uint32_t)(tx)) : "memory")
#define MBARRIER_ARRIVE(mbar)                                                 \
  asm volatile("mbarrier.arrive.shared.b64 _, [%0];"                          \
               :: "r"((uint32_t)(mbar)) : "memory")
#define MBARRIER_WAIT_PARITY(mbar_addr, phase_parity) do {                    \
  uint32_t _mbar = (uint32_t)(mbar_addr);                                     \
  uint32_t _par = (uint32_t)(phase_parity);                                   \
  uint32_t _done;                                                             \
  asm volatile(                                                               \
      "{\n\t.reg .pred p;\n\t"                                                \
      "mbarrier.try_wait.parity.acquire.cta.shared::cta.b64 p, [%1], %2;\n\t" \
      "selp.b32 %0, 1, 0, p;\n\t}"                                            \
      : "=r"(_done) : "r"(_mbar), "r"(_par) : "memory");                      \
  if (!_done) {                                                               \
    asm volatile(                                                             \
        "{\n\t.reg .pred P1;\n\t"                                             \
        "WAIT_LOOP_%=:\n\t"                                                   \
        "mbarrier.try_wait.parity.acquire.cta.shared::cta.b64 P1, [%0], %1, 0x989680;\n\t" \
        "@P1 bra.uni WAIT_DONE_%=;\n\t"                                       \
        "bra.uni WAIT_LOOP_%=;\n\t"                                           \
        "WAIT_DONE_%=:\n\t}"                                                  \
        :: "r"(_mbar), "r"(_par) : "memory");                                 \
  }                                                                           \
} while (0)

__device__ __forceinline__ void pack_hilo(float p0, float p1, uint32_t& hi,
                                          uint32_t& lo) {
  __nv_bfloat162 h = __floats2bfloat162_rn(p0, p1);
  float r0 = p0 - __bfloat162float(h.x);
  float r1 = p1 - __bfloat162float(h.y);
  __nv_bfloat162 l = __floats2bfloat162_rn(r0, r1);
  hi = *reinterpret_cast<uint32_t*>(&h);
  lo = *reinterpret_cast<uint32_t*>(&l);
}

// ---------------------------------------------------------------------------
// Fused pack with 4-way MLP.
// ---------------------------------------------------------------------------
#define NQ8  (BATCH * TQ * D_MODEL / 8)    // 524288
#define NKV8 (BATCH * SKV * D_MODEL / 8)   // 1048576
#define NW8  (D_MODEL * D_MODEL / 8)       // 131072
#define PSTRIDE 524288

__global__ void pack_all4(const float* __restrict__ query,
                          const float* __restrict__ key_value,
                          const float* __restrict__ w0,
                          const float* __restrict__ w1,
                          const float* __restrict__ w2,
                          const float* __restrict__ w3,
                          __nv_bfloat16* __restrict__ qh,
                          __nv_bfloat16* __restrict__ ql,
                          __nv_bfloat16* __restrict__ kvh,
                          __nv_bfloat16* __restrict__ kvl,
                          __nv_bfloat16* __restrict__ wph,
                          __nv_bfloat16* __restrict__ wpl) {
  int id = blockIdx.x * blockDim.x + threadIdx.x;
  const float* s0 = query + (size_t)id * 8;
  const float* s1 = key_value + (size_t)id * 8;
  const float* s2 = key_value + ((size_t)id + PSTRIDE) * 8;
  int w = id >> 17, wi = id & (NW8 - 1);
  const float* s3 = (w == 0 ? w0 : w == 1 ? w1 : w == 2 ? w2 : w3) +
                    (size_t)wi * 8;
  float4 a0 = *(const float4*)s0, b0 = *(const float4*)(s0 + 4);
  float4 a1 = *(const float4*)s1, b1 = *(const float4*)(s1 + 4);
  float4 a2 = *(const float4*)s2, b2 = *(const float4*)(s2 + 4);
  float4 a3 = *(const float4*)s3, b3 = *(const float4*)(s3 + 4);

  {
    uint32_t h0, h1, h2, h3, l0, l1, l2, l3;
    pack_hilo(a0.x, a0.y, h0, l0);
    pack_hilo(a0.z, a0.w, h1, l1);
    pack_hilo(b0.x, b0.y, h2, l2);
    pack_hilo(b0.z, b0.w, h3, l3);
    int e = id * 8;
    int m = e >> 10, k = e & 1023;
    int r = m & 127, mb = m >> 7, kc = k >> 5, seg = (k >> 3) & 3;
    size_t t = ((size_t)mb * 32 + kc) * 4096 + r * 32 +
               ((seg ^ ((r >> 1) & 3)) << 3);
    *(uint4*)(qh + t) = make_uint4(h0, h1, h2, h3);
    *(uint4*)(ql + t) = make_uint4(l0, l1, l2, l3);
  }
  {
    uint32_t h0, h1, h2, h3, l0, l1, l2, l3;
    pack_hilo(a1.x, a1.y, h0, l0);
    pack_hilo(a1.z, a1.w, h1, l1);
    pack_hilo(b1.x, b1.y, h2, l2);
    pack_hilo(b1.z, b1.w, h3, l3);
    int e = id * 8;
    int m = e >> 10, k = e & 1023;
    int r = m & 127, mb = m >> 7, kc = k >> 5, seg = (k >> 3) & 3;
    size_t t = ((size_t)mb * 32 + kc) * 4096 + r * 32 +
               ((seg ^ ((r >> 1) & 3)) << 3);
    *(uint4*)(kvh + t) = make_uint4(h0, h1, h2, h3);
    *(uint4*)(kvl + t) = make_uint4(l0, l1, l2, l3);
  }
  {
    uint32_t h0, h1, h2, h3, l0, l1, l2, l3;
    pack_hilo(a2.x, a2.y, h0, l0);
    pack_hilo(a2.z, a2.w, h1, l1);
    pack_hilo(b2.x, b2.y, h2, l2);
    pack_hilo(b2.z, b2.w, h3, l3);
    int e = (id + PSTRIDE) * 8;
    int m = e >> 10, k = e & 1023;
    int r = m & 127, mb = m >> 7, kc = k >> 5, seg = (k >> 3) & 3;
    size_t t = ((size_t)mb * 32 + kc) * 4096 + r * 32 +
               ((seg ^ ((r >> 1) & 3)) << 3);
    *(uint4*)(kvh + t) = make_uint4(h0, h1, h2, h3);
    *(uint4*)(kvl + t) = make_uint4(l0, l1, l2, l3);
  }
  {
    uint32_t h0, h1, h2, h3, l0, l1, l2, l3;
    pack_hilo(a3.x, a3.y, h0, l0);
    pack_hilo(a3.z, a3.w, h1, l1);
    pack_hilo(b3.x, b3.y, h2, l2);
    pack_hilo(b3.z, b3.w, h3, l3);
    int e = wi * 8;
    int m = e >> 10, k = e & 1023;
    int r = m & 127, mb = m >> 7, kc = k >> 5, seg = (k >> 3) & 3;
    size_t t = (size_t)w * D_MODEL * D_MODEL +
               ((size_t)mb * 32 + kc) * 4096 + r * 32 +
               ((seg ^ ((r >> 1) & 3)) << 3);
    *(uint4*)(wph + t) = make_uint4(h0, h1, h2, h3);
    *(uint4*)(wpl + t) = make_uint4(l0, l1, l2, l3);
  }
}

// ---------------------------------------------------------------------------
// GEMM core (unchanged, round-9 proven): bf16x3 NT, 3-stage bulk-DMA.
// ---------------------------------------------------------------------------
#define NCH      32
#define GS_TILE  8192
#define GS_STAGE 32768
#define GS_FULL  98304
#define GS_EMPTY 98328
#define GS_SMEM  98432

__device__ __forceinline__ void gemm_mainloop(
    const __nv_bfloat16* Ah, const __nv_bfloat16* Al,
    const __nv_bfloat16* Bh, const __nv_bfloat16* Bl,
    int mb, int nb, uint32_t sb, int tid, int lane, int warp,
    float acc[2][8][4]) {
  const int wm = (warp & 3) * 32;
  const int wn = (warp >> 2) * 64;

  if (tid == 0) {
#pragma unroll
    for (int s = 0; s < 3; s++) {
      MBARRIER_INIT(sb + GS_FULL + s * 8, 1);
      MBARRIER_INIT(sb + GS_EMPTY + s * 8, 8);
    }
  }
  __syncthreads();

#define G_BULK(c_, s_) do {                                                   \
    uint32_t fb_ = sb + GS_FULL + (s_) * 8;                                   \
    MBARRIER_EXPECT_TX(fb_, 32768u);                                          \
    uint32_t d_ = sb + (uint32_t)(s_) * GS_STAGE;                             \
    bulk_g2s(d_,             Ah + ((size_t)(mb * NCH + (c_))) * 4096, 8192u, fb_); \
    bulk_g2s(d_ + GS_TILE,   Al + ((size_t)(mb * NCH + (c_))) * 4096, 8192u, fb_); \
    bulk_g2s(d_ + 2*GS_TILE, Bh + ((size_t)(nb * NCH + (c_))) * 4096, 8192u, fb_); \
    bulk_g2s(d_ + 3*GS_TILE, Bl + ((size_t)(nb * NCH + (c_))) * 4096, 8192u, fb_); \
  } while (0)

  if (tid == 0) {
    G_BULK(0, 0);
    G_BULK(1, 1);
  }

  const int ar = lane & 15;
  const int ac = ((lane >> 4) & 1) * 8;
  const int nof = ((lane >> 4) & 1) * 8 + (lane & 7);
  const int kof2 = ((lane >> 3) & 1) * 8;

  for (int c = 0; c < NCH; c++) {
    const int cur = c % 3;
    const int cp = c + 2;
    if (cp < NCH && tid == 0) {
      const int sp = cp % 3;
      if (cp >= 3)
        MBARRIER_WAIT_PARITY(sb + GS_EMPTY + sp * 8, ((cp / 3) - 1) & 1);
      G_BULK(cp, sp);
    }
    MBARRIER_WAIT_PARITY(sb + GS_FULL + cur * 8, (c / 3) & 1);

    const uint32_t st = sb + (uint32_t)cur * GS_STAGE;
#pragma unroll
    for (int ks = 0; ks < 2; ks++) {
      const int k0 = ks * 16;
      uint32_t afh[2][4], afl[2][4];
#pragma unroll
      for (int mi = 0; mi < 2; mi++) {
        int r = wm + mi * 16 + ar;
        int seg = (k0 + ac) >> 3;
        uint32_t ad = st + (uint32_t)(r * 64 + ((seg ^ ((r >> 1) & 3)) << 4));
        ldsm4(afh[mi], ad);
        ldsm4(afl[mi], ad + GS_TILE);
      }
#pragma unroll
      for (int ni = 0; ni < 4; ni++) {
        int rb = wn + ni * 16 + nof;
        int segb = (k0 + kof2) >> 3;
        uint32_t bd = st + 2 * GS_TILE +
                      (uint32_t)(rb * 64 + ((segb ^ ((rb >> 1) & 3)) << 4));
        uint32_t bh[4], bl[4];
        ldsm4(bh, bd);
        ldsm4(bl, bd + GS_TILE);
#pragma unroll
        for (int mi = 0; mi < 2; mi++)
#pragma unroll
          for (int hh = 0; hh < 2; hh++) {
            int nj = ni * 2 + hh;
            mma16816(acc[mi][nj], afh[mi], &bh[2 * hh]);
            mma16816(acc[mi][nj], afh[mi], &bl[2 * hh]);
            mma16816(acc[mi][nj], afl[mi], &bh[2 * hh]);
          }
      }
    }
    if (lane == 0) MBARRIER_ARRIVE(sb + GS_EMPTY + cur * 8);
  }
#undef G_BULK
}

// ---------------------------------------------------------------------------
// Fused Q/K/V projection: 1280 CTAs, runtime mode decode (unchanged).
// ---------------------------------------------------------------------------
__global__ __launch_bounds__(256, 2)
void proj_fused(const __nv_bfloat16* __restrict__ qh,
                const __nv_bfloat16* __restrict__ ql,
                const __nv_bfloat16* __restrict__ kvh,
                const __nv_bfloat16* __restrict__ kvl,
                const __nv_bfloat16* __restrict__ wph,
                const __nv_bfloat16* __restrict__ wpl,
                __nv_bfloat16* __restrict__ yh,
                __nv_bfloat16* __restrict__ yl,
                __nv_bfloat16* __restrict__ kfh,
                __nv_bfloat16* __restrict__ kfl,
                __nv_bfloat16* __restrict__ vth,
                __nv_bfloat16* __restrict__ vtl) {
  extern __shared__ __align__(128) char sm[];
  const uint32_t sb = smem_u32(sm);
  const int tid = threadIdx.x, lane = tid & 31, warp = tid >> 5;
  const size_t WSZ = (size_t)D_MODEL * D_MODEL;

  int id = blockIdx.x;
  int mode, bx, by;
  const __nv_bfloat16 *Ah, *Al, *Bh, *Bl;
  __nv_bfloat16 *Ph, *Pl;
  if (id < 256) {
    mode = 1; bx = id & 7; by = id >> 3;
    Ah = qh; Al = ql; Bh = wph; Bl = wpl; Ph = yh; Pl = yl;
  } else if (id < 768) {
    mode = 2; id -= 256; bx = id & 7; by = id >> 3;
    Ah = kvh; Al = kvl; Bh = wph + WSZ; Bl = wpl + WSZ; Ph = kfh; Pl = kfl;
  } else {
    mode = 3; id -= 768; bx = id & 63; by = id >> 6;
    Ah = wph + 2 * WSZ; Al = wpl + 2 * WSZ; Bh = kvh; Bl = kvl;
    Ph = vth; Pl = vtl;
  }
  const int bm = by * 128, bn = bx * 128;

  float acc[2][8][4];
#pragma unroll
  for (int mi = 0; mi < 2; mi++)
#pragma unroll
    for (int nj = 0; nj < 8; nj++)
#pragma unroll
      for (int q = 0; q < 4; q++) acc[mi][nj][q] = 0.0f;

  gemm_mainloop(Ah, Al, Bh, Bl, by, bx, sb, tid, lane, warp, acc);

  const int wm = (warp & 3) * 32;
  const int wn = (warp >> 2) * 64;
  const int crow = lane >> 2;
  const int ccol = (lane & 3) * 2;
#pragma unroll
  for (int mi = 0; mi < 2; mi++)
#pragma unroll
    for (int nj = 0; nj < 8; nj++) {
      int m0 = bm + wm + mi * 16 + crow;
      int cc = bn + wn + nj * 8 + ccol;
#pragma unroll
      for (int half = 0; half < 2; half++) {
        int m = m0 + half * 8;
        float v0 = acc[mi][nj][half * 2], v1 = acc[mi][nj][half * 2 + 1];
        size_t t;
        if (mode == 1) {
          int b = m >> 11, q = m & 2047;
          int h = cc >> 6, dd = cc & 63;
          t = ((size_t)(b * 16 + h) * 16 + (q >> 7)) * 8192 +
              (size_t)(q & 127) * 64 + (((dd >> 3) ^ (q & 7)) << 3) + (dd & 7);
        } else if (mode == 2) {
          int b = m >> 12, s = m & 4095;
          int h = cc >> 6, dd = cc & 63;
          t = ((size_t)(b * 16 + h) * 64 + (s >> 6)) * 4096 +
              (size_t)(s & 63) * 64 + (((dd >> 3) ^ (s & 7)) << 3) + (dd & 7);
        } else {
          int h = m >> 6, dr = m & 63;
          int b = cc >> 12, s = cc & 4095;
          t = ((size_t)(b * 16 + h) * 64 + (s >> 6)) * 4096 +
              (size_t)dr * 64 + ((((s >> 3) & 7) ^ (dr & 7)) << 3) + (s & 7);
        }
        uint32_t hi, lo;
        pack_hilo(v0, v1, hi, lo);
        *(uint32_t*)(Ph + t) = hi;
        *(uint32_t*)(Pl + t) = lo;
      }
    }
}

// ---------------------------------------------------------------------------
// Output projection (unchanged).
// ---------------------------------------------------------------------------
__global__ __launch_bounds__(256, 2)
void gemm_out(const __nv_bfloat16* __restrict__ Ah,
              const __nv_bfloat16* __restrict__ Al,
              const __nv_bfloat16* __restrict__ Bh,
              const __nv_bfloat16* __restrict__ Bl,
              float* __restrict__ C, int N) {
  extern __shared__ __align__(128) char sm[];
  const uint32_t sb = smem_u32(sm);
  const int tid = threadIdx.x, lane = tid & 31, warp = tid >> 5;
  const int bm = blockIdx.y * 128;
  const int bn = blockIdx.x * 128;

  float acc[2][8][4];
#pragma unroll
  for (int mi = 0; mi < 2; mi++)
#pragma unroll
    for (int nj = 0; nj < 8; nj++)
#pragma unroll
      for (int q = 0; q < 4; q++) acc[mi][nj][q] = 0.0f;

  gemm_mainloop(Ah, Al, Bh, Bl, blockIdx.y, blockIdx.x, sb, tid, lane, warp, acc);

  const int wm = (warp & 3) * 32;
  const int wn = (warp >> 2) * 64;
  const int crow = lane >> 2;
  const int ccol = (lane & 3) * 2;
#pragma unroll
  for (int mi = 0; mi < 2; mi++)
#pragma unroll
    for (int nj = 0; nj < 8; nj++) {
      int r0 = bm + wm + mi * 16 + crow;
      int cc = bn + wn + nj * 8 + ccol;
      *(float2*)(C + (size_t)r0 * N + cc) =
          make_float2(acc[mi][nj][0], acc[mi][nj][1]);
      *(float2*)(C + (size_t)(r0 + 8) * N + cc) =
          make_float2(acc[mi][nj][2], acc[mi][nj][3]);
    }
}

// ---------------------------------------------------------------------------
// HMMA flash attention at 2 CTAs/SM. 2-stage KV pipeline; Q PARKED in smem
// (re-ldsm per tile). FIX vs round 15: preload ONLY stage 0 — the loop's
// cp=t+1 prefetch fills stage 1 at t=0 (round 15 double-filled it -> ULF).
// ---------------------------------------------------------------------------
#define FS_TILE  8192
#define FS_STAGE 32768
#define FS_QOFF  65536
#define FS_FULL  98304
#define FS_EMPTY 98320
#define FS_SMEM  98432

__global__ __launch_bounds__(256, 2)
void flash_bulk(const __nv_bfloat16* __restrict__ qfh,
                const __nv_bfloat16* __restrict__ qfl,
                const __nv_bfloat16* __restrict__ kfh,
                const __nv_bfloat16* __restrict__ kfl,
                const __nv_bfloat16* __restrict__ vth,
                const __nv_bfloat16* __restrict__ vtl,
                const float* __restrict__ imp,
                __nv_bfloat16* __restrict__ Yh,
                __nv_bfloat16* __restrict__ Yl) {
  extern __shared__ __align__(128) char fsm[];
  const uint32_t sb = smem_u32(fsm);
  const int b = blockIdx.z, h = blockIdx.y, qb = blockIdx.x;
  const int q0 = qb * 128;
  const int tid = threadIdx.x, lane = tid & 31, warp = tid >> 5;
  const int wm = warp * 16;

  if (tid == 0) {
#pragma unroll
    for (int s = 0; s < 2; s++) {
      MBARRIER_INIT(sb + FS_FULL + s * 8, 1);
      MBARRIER_INIT(sb + FS_EMPTY + s * 8, 8);
    }
  }
  // Stage Q (persistent; hi at FS_QOFF, lo at +16KB).
  {
    const __nv_bfloat16* qsrc = qfh + ((size_t)(b * 16 + h) * 16 + qb) * 8192;
    const __nv_bfloat16* qsrc2 = qfl + ((size_t)(b * 16 + h) * 16 + qb) * 8192;
#pragma unroll
    for (int j = 0; j < 4; j++) {
      int idx = tid + j * 256;
      cp16(sb + FS_QOFF + idx * 16, qsrc + idx * 8);
      cp16(sb + FS_QOFF + 16384 + idx * 16, qsrc2 + idx * 8);
    }
  }
  CP_COMMIT();
  __syncthreads();              // mbar init visible

  const __nv_bfloat16* Kb = kfh + ((size_t)(b * 16 + h) * 64) * 4096;
  const __nv_bfloat16* Kb2 = kfl + ((size_t)(b * 16 + h) * 64) * 4096;
  const __nv_bfloat16* Vb = vth + ((size_t)(b * 16 + h) * 64) * 4096;
  const __nv_bfloat16* Vb2 = vtl + ((size_t)(b * 16 + h) * 64) * 4096;

#define F_BULK(t_, s_) do {                                                   \
    uint32_t fb_ = sb + FS_FULL + (s_) * 8;                                   \
    MBARRIER_EXPECT_TX(fb_, 32768u);                                          \
    uint32_t d_ = sb + (uint32_t)(s_) * FS_STAGE;                             \
    bulk_g2s(d_,             Kb  + (size_t)(t_) * 4096, 8192u, fb_);          \
    bulk_g2s(d_ + FS_TILE,   Kb2 + (size_t)(t_) * 4096, 8192u, fb_);          \
    bulk_g2s(d_ + 2*FS_TILE, Vb  + (size_t)(t_) * 4096, 8192u, fb_);          \
    bulk_g2s(d_ + 3*FS_TILE, Vb2 + (size_t)(t_) * 4096, 8192u, fb_);          \
  } while (0)

  if (tid == 0) {
    F_BULK(0, 0);               // ONLY stage 0 here (stage 1 filled at t=0)
  }

  const int ar = lane & 15;
  const int ac = ((lane >> 4) & 1) * 8;
  const int nof = ((lane >> 4) & 1) * 8 + (lane & 7);
  const int kof2 = ((lane >> 3) & 1) * 8;

  asm volatile("cp.async.wait_group 0;");
  __syncthreads();              // Q visible to all warps

  const int q2 = (lane & 3) * 2;
  float lg[4];
  lg[0] = logf(fmaxf(imp[b * NHEADS + (q2 & 15)], 1e-6f));
  lg[1] = logf(fmaxf(imp[b * NHEADS + ((q2 + 1) & 15)], 1e-6f));
  lg[2] = logf(fmaxf(imp[b * NHEADS + ((q2 + 8) & 15)], 1e-6f));
  lg[3] = logf(fmaxf(imp[b * NHEADS + ((q2 + 9) & 15)], 1e-6f));

  float m0 = -INFINITY, m1 = -INFINITY, l0 = 0.0f, l1 = 0.0f;
  float y[8][4];
#pragma unroll
  for (int nf = 0; nf < 8; nf++)
#pragma unroll
    for (int q = 0; q < 4; q++) y[nf][q] = 0.0f;

  const int NT = SKV / 64;
  for (int t = 0; t < NT; t++) {
    const int cur = t & 1;
    const int cp = t + 1;
    if (cp < NT && tid == 0) {
      const int sp = cp & 1;
      if (cp >= 2)
        MBARRIER_WAIT_PARITY(sb + FS_EMPTY + sp * 8, ((cp >> 1) - 1) & 1);
      F_BULK(cp, sp);
    }
    MBARRIER_WAIT_PARITY(sb + FS_FULL + cur * 8, (t >> 1) & 1);
    const uint32_t st = sb + (uint32_t)cur * FS_STAGE;

    // ---- S = Q K^T (Q fragments re-loaded from parked smem per kc) ----
    float s[8][4];
#pragma unroll
    for (int nf = 0; nf < 8; nf++)
#pragma unroll
      for (int q = 0; q < 4; q++) s[nf][q] = 0.0f;
#pragma unroll
    for (int kc = 0; kc < 4; kc++) {
      uint32_t qa[4], qlo[4];
      {
        int r = wm + ar;
        int seg = 2 * kc + (ac >> 3);
        uint32_t ad = sb + FS_QOFF +
                      (uint32_t)(r * 128 + ((seg ^ (r & 7)) << 4));
        ldsm4(qa, ad);
        ldsm4(qlo, ad + 16384);
      }
#pragma unroll
      for (int n2 = 0; n2 < 4; n2++) {
        int r = n2 * 16 + nof;
        int seg = 2 * kc + (kof2 >> 3);
        uint32_t bd = st + (uint32_t)(r * 128 + ((seg ^ (r & 7)) << 4));
        uint32_t bh[4], bl[4];
        ldsm4(bh, bd);
        ldsm4(bl, bd + FS_TILE);
#pragma unroll
        for (int hh = 0; hh < 2; hh++) {
          mma16816(s[n2 * 2 + hh], qa, &bh[2 * hh]);
          mma16816(s[n2 * 2 + hh], qa, &bl[2 * hh]);
          mma16816(s[n2 * 2 + hh], qlo, &bh[2 * hh]);
        }
      }
    }

    float mt0 = -INFINITY, mt1 = -INFINITY;
#pragma unroll
    for (int nf = 0; nf < 8; nf++) {
      const int p = (nf & 1) * 2;
      s[nf][0] = s[nf][0] * 0.125f + lg[p];
      s[nf][1] = s[nf][1] * 0.125f + lg[p + 1];
      s[nf][2] = s[nf][2] * 0.125f + lg[p];
      s[nf][3] = s[nf][3] * 0.125f + lg[p + 1];
      mt0 = fmaxf(mt0, fmaxf(s[nf][0], s[nf][1]));
      mt1 = fmaxf(mt1, fmaxf(s[nf][2], s[nf][3]));
    }
    mt0 = fmaxf(mt0, __shfl_xor_sync(0xffffffffu, mt0, 1));
    mt0 = fmaxf(mt0, __shfl_xor_sync(0xffffffffu, mt0, 2));
    mt1 = fmaxf(mt1, __shfl_xor_sync(0xffffffffu, mt1, 1));
    mt1 = fmaxf(mt1, __shfl_xor_sync(0xffffffffu, mt1, 2));

    float mn0 = fmaxf(m0, mt0), mn1 = fmaxf(m1, mt1);
    float c0 = __expf(m0 - mn0), c1 = __expf(m1 - mn1);
    m0 = mn0; m1 = mn1;

    uint32_t ph[4][4], pl[4][4];
    float r0 = 0.0f, r1 = 0.0f;
#pragma unroll
    for (int nf = 0; nf < 8; nf++) {
      float p0 = __expf(s[nf][0] - m0);
      float p1 = __expf(s[nf][1] - m0);
      float p2 = __expf(s[nf][2] - m1);
      float p3 = __expf(s[nf][3] - m1);
      r0 += p0 + p1;
      r1 += p2 + p3;
      const int kc = nf >> 1, o = (nf & 1) * 2;
      pack_hilo(p0, p1, ph[kc][o], pl[kc][o]);
      pack_hilo(p2, p3, ph[kc][o + 1], pl[kc][o + 1]);
    }
    r0 += __shfl_xor_sync(0xffffffffu, r0, 1);
    r0 += __shfl_xor_sync(0xffffffffu, r0, 2);
    r1 += __shfl_xor_sync(0xffffffffu, r1, 1);
    r1 += __shfl_xor_sync(0xffffffffu, r1, 2);
    l0 = l0 * c0 + r0;
    l1 = l1 * c1 + r1;
#pragma unroll
    for (int nf = 0; nf < 8; nf++) {
      y[nf][0] *= c0; y[nf][1] *= c0;
      y[nf][2] *= c1; y[nf][3] *= c1;
    }

#pragma unroll
    for (int kc = 0; kc < 4; kc++) {
#pragma unroll
      for (int n2 = 0; n2 < 4; n2++) {
        int r = n2 * 16 + nof;
        int seg = 2 * kc + (kof2 >> 3);
        uint32_t bd = st + 2 * FS_TILE +
                      (uint32_t)(r * 128 + ((seg ^ (r & 7)) << 4));
        uint32_t vh[4], vl[4];
        ldsm4(vh, bd);
        ldsm4(vl, bd + FS_TILE);
#pragma unroll
        for (int hh = 0; hh < 2; hh++) {
          mma16816(y[n2 * 2 + hh], ph[kc], &vh[2 * hh]);
          mma16816(y[n2 * 2 + hh], ph[kc], &vl[2 * hh]);
          mma16816(y[n2 * 2 + hh], pl[kc], &vh[2 * hh]);
        }
      }
    }
    if (lane == 0) MBARRIER_ARRIVE(sb + FS_EMPTY + cur * 8);
  }

  const float i0 = 1.0f / l0, i1 = 1.0f / l1;
  const int row0 = q0 + wm + (lane >> 2);
#pragma unroll
  for (int nf = 0; nf < 8; nf++) {
    int k = h * HDIM + 8 * nf + q2;
    int kc = k >> 5, seg0 = (k >> 3) & 3, klow = k & 7;
#pragma unroll
    for (int half = 0; half < 2; half++) {
      int m = b * TQ + row0 + half * 8;
      float v0 = y[nf][half * 2] * (half ? i1 : i0);
      float v1 = y[nf][half * 2 + 1] * (half ? i1 : i0);
      int r = m & 127, mb2 = m >> 7;
      size_t t = ((size_t)mb2 * 32 + kc) * 4096 + (size_t)r * 32 +
                 ((seg0 ^ ((r >> 1) & 3)) << 3) + klow;
      uint32_t hi, lo;
      pack_hilo(v0, v1, hi, lo);
      *(uint32_t*)(Yh + t) = hi;
      *(uint32_t*)(Yl + t) = lo;
    }
  }
}

// ---------------------------------------------------------------------------
extern "C" void kernel_launch(void* const* d_in, const int* in_sizes, int n_in,
                              void* d_out, int out_size) {
  const float* query     = (const float*)d_in[0];
  const float* key_value = (const float*)d_in[1];
  const float* imp       = (const float*)d_in[2];
  const float* Wq        = (const float*)d_in[3];
  const float* Wk        = (const float*)d_in[4];
  const float* Wv        = (const float*)d_in[5];
  const float* Wo        = (const float*)d_in[6];
  float* out = (float*)d_out;

  __nv_bfloat16 *qh, *ql, *kvh, *kvl, *yh, *yl, *wh, *wl, *kfh, *kfl, *vth, *vtl;
  cudaGetSymbolAddress((void**)&qh, g_qh);
  cudaGetSymbolAddress((void**)&ql, g_ql);
  cudaGetSymbolAddress((void**)&kvh, g_kvh);
  cudaGetSymbolAddress((void**)&kvl, g_kvl);
  cudaGetSymbolAddress((void**)&yh, g_yh);
  cudaGetSymbolAddress((void**)&yl, g_yl);
  cudaGetSymbolAddress((void**)&wh, g_wh);
  cudaGetSymbolAddress((void**)&wl, g_wl);
  cudaGetSymbolAddress((void**)&kfh, g_kfh);
  cudaGetSymbolAddress((void**)&kfl, g_kfl);
  cudaGetSymbolAddress((void**)&vth, g_vth);
  cudaGetSymbolAddress((void**)&vtl, g_vtl);
  const size_t WSZ = (size_t)D_MODEL * D_MODEL;

  cudaFuncSetAttribute(proj_fused,
                       cudaFuncAttributeMaxDynamicSharedMemorySize, GS_SMEM);
  cudaFuncSetAttribute(gemm_out,
                       cudaFuncAttributeMaxDynamicSharedMemorySize, GS_SMEM);
  cudaFuncSetAttribute(flash_bulk,
                       cudaFuncAttributeMaxDynamicSharedMemorySize, FS_SMEM);

  pack_all4<<<PSTRIDE / 256, 256>>>(query, key_value, Wq, Wk, Wv, Wo,
                                    qh, ql, kvh, kvl, wh, wl);

  proj_fused<<<1280, 256, GS_SMEM>>>(qh, ql, kvh, kvl, wh, wl,
                                     yh, yl, kfh, kfl, vth, vtl);

  flash_bulk<<<dim3(TQ / 128, NHEADS, BATCH), 256, FS_SMEM>>>(
      yh, yl, kfh, kfl, vth, vtl, imp, qh, ql);

  gemm_out<<<dim3(8, 32), 256, GS_SMEM>>>(
      qh, ql, wh + 3 * WSZ, wl + 3 * WSZ, out, D_MODEL);
}

// round 17
// speedup vs baseline: 1.1076x; 1.0930x over previous
#include <cuda_runtime.h>
#include <cuda_bf16.h>
#include <cuda_fp16.h>
#include <cstdint>
#include <math.h>

#define D_MODEL 1024
#define BATCH   2
#define TQ      2048
#define SKV     4096
#define NHEADS  16
#define HDIM    64

// ---------------- scratch (no cudaMalloc allowed) ----------------
__device__ __align__(256) __nv_bfloat16 g_qh[(size_t)BATCH * TQ  * D_MODEL];
__device__ __align__(256) __nv_bfloat16 g_ql[(size_t)BATCH * TQ  * D_MODEL];
__device__ __align__(256) __nv_bfloat16 g_kvh[(size_t)BATCH * SKV * D_MODEL];
__device__ __align__(256) __nv_bfloat16 g_kvl[(size_t)BATCH * SKV * D_MODEL];
__device__ __align__(256) __nv_bfloat16 g_yh[(size_t)BATCH * TQ  * D_MODEL];  // flash-Q fp16 hi
__device__ __align__(256) __nv_bfloat16 g_yl[(size_t)BATCH * TQ  * D_MODEL];  // flash-Q fp16 lo
__device__ __align__(256) __nv_bfloat16 g_wh[4][(size_t)D_MODEL * D_MODEL];
__device__ __align__(256) __nv_bfloat16 g_wl[4][(size_t)D_MODEL * D_MODEL];
__device__ __align__(256) __nv_bfloat16 g_kfh[(size_t)BATCH * SKV * D_MODEL];  // flash-K fp16 (single)
__device__ __align__(256) __nv_bfloat16 g_kfl[(size_t)BATCH * SKV * D_MODEL];  // unused now
__device__ __align__(256) __nv_bfloat16 g_vth[(size_t)BATCH * NHEADS * HDIM * SKV];
__device__ __align__(256) __nv_bfloat16 g_vtl[(size_t)BATCH * NHEADS * HDIM * SKV];

// ---------------- primitives ----------------
__device__ __forceinline__ uint32_t smem_u32(const void* p) {
  uint32_t a;
  asm("{ .reg .u64 t; cvta.to.shared.u64 t, %1; cvt.u32.u64 %0, t; }"
      : "=r"(a) : "l"(p));
  return a;
}
__device__ __forceinline__ void ldsm4(uint32_t* r, uint32_t a) {
  asm volatile("ldmatrix.sync.aligned.m8n8.x4.shared.b16 {%0,%1,%2,%3}, [%4];"
               : "=r"(r[0]), "=r"(r[1]), "=r"(r[2]), "=r"(r[3]) : "r"(a));
}
__device__ __forceinline__ void mma16816(float* d, const uint32_t* a,
                                         const uint32_t* b) {
  asm volatile(
      "mma.sync.aligned.m16n8k16.row.col.f32.bf16.bf16.f32 "
      "{%0,%1,%2,%3}, {%4,%5,%6,%7}, {%8,%9}, {%0,%1,%2,%3};"
      : "+f"(d[0]), "+f"(d[1]), "+f"(d[2]), "+f"(d[3])
      : "r"(a[0]), "r"(a[1]), "r"(a[2]), "r"(a[3]), "r"(b[0]), "r"(b[1]));
}
__device__ __forceinline__ void mma16816_f16(float* d, const uint32_t* a,
                                             const uint32_t* b) {
  asm volatile(
      "mma.sync.aligned.m16n8k16.row.col.f32.f16.f16.f32 "
      "{%0,%1,%2,%3}, {%4,%5,%6,%7}, {%8,%9}, {%0,%1,%2,%3};"
      : "+f"(d[0]), "+f"(d[1]), "+f"(d[2]), "+f"(d[3])
      : "r"(a[0]), "r"(a[1]), "r"(a[2]), "r"(a[3]), "r"(b[0]), "r"(b[1]));
}
__device__ __forceinline__ void cp16(uint32_t dst, const void* src) {
  asm volatile("cp.async.cg.shared.global [%0], [%1], 16;" :: "r"(dst), "l"(src));
}
#define CP_COMMIT() asm volatile("cp.async.commit_group;")

__device__ __forceinline__ void bulk_g2s(uint32_t dst, const void* src,
                                         uint32_t bytes, uint32_t mbar) {
  asm volatile(
      "cp.async.bulk.shared::cluster.global.mbarrier::complete_tx::bytes "
      "[%0], [%1], %2, [%3];"
      :: "r"(dst), "l"(src), "r"(bytes), "r"(mbar) : "memory");
}
#define MBARRIER_INIT(mbar, count)                                            \
  asm volatile("mbarrier.init.shared.b64 [%0], %1;"                           \
               :: "r"((uint32_t)(mbar)), "r"((uint32_t)(count)) : "memory")
#define MBARRIER_EXPECT_TX(mbar, tx)                                          \
  asm volatile("mbarrier.arrive.expect_tx.shared.b64 _, [%0], %1;"            \
               :: "r"((uint32_t)(mbar)), "r"((uint32_t)(tx)) : "memory")
#define MBARRIER_ARRIVE(mbar)                                                 \
  asm volatile("mbarrier.arrive.shared.b64 _, [%0];"                          \
               :: "r"((uint32_t)(mbar)) : "memory")
#define MBARRIER_WAIT_PARITY(mbar_addr, phase_parity) do {                    \
  uint32_t _mbar = (uint32_t)(mbar_addr);                                     \
  uint32_t _par = (uint32_t)(phase_parity);                                   \
  uint32_t _done;                                                             \
  asm volatile(                                                               \
      "{\n\t.reg .pred p;\n\t"                                                \
      "mbarrier.try_wait.parity.acquire.cta.shared::cta.b64 p, [%1], %2;\n\t" \
      "selp.b32 %0, 1, 0, p;\n\t}"                                            \
      : "=r"(_done) : "r"(_mbar), "r"(_par) : "memory");                      \
  if (!_done) {                                                               \
    asm volatile(                                                             \
        "{\n\t.reg .pred P1;\n\t"                                             \
        "WAIT_LOOP_%=:\n\t"                                                   \
        "mbarrier.try_wait.parity.acquire.cta.shared::cta.b64 P1, [%0], %1, 0x989680;\n\t" \
        "@P1 bra.uni WAIT_DONE_%=;\n\t"                                       \
        "bra.uni WAIT_LOOP_%=;\n\t"                                           \
        "WAIT_DONE_%=:\n\t}"                                                  \
        :: "r"(_mbar), "r"(_par) : "memory");                                 \
  }                                                                           \
} while (0)

__device__ __forceinline__ void pack_hilo(float p0, float p1, uint32_t& hi,
                                          uint32_t& lo) {
  __nv_bfloat162 h = __floats2bfloat162_rn(p0, p1);
  float r0 = p0 - __bfloat162float(h.x);
  float r1 = p1 - __bfloat162float(h.y);
  __nv_bfloat162 l = __floats2bfloat162_rn(r0, r1);
  hi = *reinterpret_cast<uint32_t*>(&h);
  lo = *reinterpret_cast<uint32_t*>(&l);
}
__device__ __forceinline__ void pack_hilo_f16(float p0, float p1, uint32_t& hi,
                                              uint32_t& lo) {
  __half2 h = __floats2half2_rn(p0, p1);
  float r0 = p0 - __low2float(h);
  float r1 = p1 - __high2float(h);
  __half2 l = __floats2half2_rn(r0, r1);
  hi = *reinterpret_cast<uint32_t*>(&h);
  lo = *reinterpret_cast<uint32_t*>(&l);
}

// ---------------------------------------------------------------------------
// Fused pack with 4-way MLP (unchanged; GEMM operands remain bf16).
// ---------------------------------------------------------------------------
#define NQ8  (BATCH * TQ * D_MODEL / 8)
#define NKV8 (BATCH * SKV * D_MODEL / 8)
#define NW8  (D_MODEL * D_MODEL / 8)
#define PSTRIDE 524288

__global__ void pack_all4(const float* __restrict__ query,
                          const float* __restrict__ key_value,
                          const float* __restrict__ w0,
                          const float* __restrict__ w1,
                          const float* __restrict__ w2,
                          const float* __restrict__ w3,
                          __nv_bfloat16* __restrict__ qh,
                          __nv_bfloat16* __restrict__ ql,
                          __nv_bfloat16* __restrict__ kvh,
                          __nv_bfloat16* __restrict__ kvl,
                          __nv_bfloat16* __restrict__ wph,
                          __nv_bfloat16* __restrict__ wpl) {
  int id = blockIdx.x * blockDim.x + threadIdx.x;
  const float* s0 = query + (size_t)id * 8;
  const float* s1 = key_value + (size_t)id * 8;
  const float* s2 = key_value + ((size_t)id + PSTRIDE) * 8;
  int w = id >> 17, wi = id & (NW8 - 1);
  const float* s3 = (w == 0 ? w0 : w == 1 ? w1 : w == 2 ? w2 : w3) +
                    (size_t)wi * 8;
  float4 a0 = *(const float4*)s0, b0 = *(const float4*)(s0 + 4);
  float4 a1 = *(const float4*)s1, b1 = *(const float4*)(s1 + 4);
  float4 a2 = *(const float4*)s2, b2 = *(const float4*)(s2 + 4);
  float4 a3 = *(const float4*)s3, b3 = *(const float4*)(s3 + 4);

  {
    uint32_t h0, h1, h2, h3, l0, l1, l2, l3;
    pack_hilo(a0.x, a0.y, h0, l0);
    pack_hilo(a0.z, a0.w, h1, l1);
    pack_hilo(b0.x, b0.y, h2, l2);
    pack_hilo(b0.z, b0.w, h3, l3);
    int e = id * 8;
    int m = e >> 10, k = e & 1023;
    int r = m & 127, mb = m >> 7, kc = k >> 5, seg = (k >> 3) & 3;
    size_t t = ((size_t)mb * 32 + kc) * 4096 + r * 32 +
               ((seg ^ ((r >> 1) & 3)) << 3);
    *(uint4*)(qh + t) = make_uint4(h0, h1, h2, h3);
    *(uint4*)(ql + t) = make_uint4(l0, l1, l2, l3);
  }
  {
    uint32_t h0, h1, h2, h3, l0, l1, l2, l3;
    pack_hilo(a1.x, a1.y, h0, l0);
    pack_hilo(a1.z, a1.w, h1, l1);
    pack_hilo(b1.x, b1.y, h2, l2);
    pack_hilo(b1.z, b1.w, h3, l3);
    int e = id * 8;
    int m = e >> 10, k = e & 1023;
    int r = m & 127, mb = m >> 7, kc = k >> 5, seg = (k >> 3) & 3;
    size_t t = ((size_t)mb * 32 + kc) * 4096 + r * 32 +
               ((seg ^ ((r >> 1) & 3)) << 3);
    *(uint4*)(kvh + t) = make_uint4(h0, h1, h2, h3);
    *(uint4*)(kvl + t) = make_uint4(l0, l1, l2, l3);
  }
  {
    uint32_t h0, h1, h2, h3, l0, l1, l2, l3;
    pack_hilo(a2.x, a2.y, h0, l0);
    pack_hilo(a2.z, a2.w, h1, l1);
    pack_hilo(b2.x, b2.y, h2, l2);
    pack_hilo(b2.z, b2.w, h3, l3);
    int e = (id + PSTRIDE) * 8;
    int m = e >> 10, k = e & 1023;
    int r = m & 127, mb = m >> 7, kc = k >> 5, seg = (k >> 3) & 3;
    size_t t = ((size_t)mb * 32 + kc) * 4096 + r * 32 +
               ((seg ^ ((r >> 1) & 3)) << 3);
    *(uint4*)(kvh + t) = make_uint4(h0, h1, h2, h3);
    *(uint4*)(kvl + t) = make_uint4(l0, l1, l2, l3);
  }
  {
    uint32_t h0, h1, h2, h3, l0, l1, l2, l3;
    pack_hilo(a3.x, a3.y, h0, l0);
    pack_hilo(a3.z, a3.w, h1, l1);
    pack_hilo(b3.x, b3.y, h2, l2);
    pack_hilo(b3.z, b3.w, h3, l3);
    int e = wi * 8;
    int m = e >> 10, k = e & 1023;
    int r = m & 127, mb = m >> 7, kc = k >> 5, seg = (k >> 3) & 3;
    size_t t = (size_t)w * D_MODEL * D_MODEL +
               ((size_t)mb * 32 + kc) * 4096 + r * 32 +
               ((seg ^ ((r >> 1) & 3)) << 3);
    *(uint4*)(wph + t) = make_uint4(h0, h1, h2, h3);
    *(uint4*)(wpl + t) = make_uint4(l0, l1, l2, l3);
  }
}

// ---------------------------------------------------------------------------
// GEMM core (unchanged, round-9 proven): bf16x3 NT, 3-stage bulk-DMA.
// ---------------------------------------------------------------------------
#define NCH      32
#define GS_TILE  8192
#define GS_STAGE 32768
#define GS_FULL  98304
#define GS_EMPTY 98328
#define GS_SMEM  98432

__device__ __forceinline__ void gemm_mainloop(
    const __nv_bfloat16* Ah, const __nv_bfloat16* Al,
    const __nv_bfloat16* Bh, const __nv_bfloat16* Bl,
    int mb, int nb, uint32_t sb, int tid, int lane, int warp,
    float acc[2][8][4]) {
  const int wm = (warp & 3) * 32;
  const int wn = (warp >> 2) * 64;

  if (tid == 0) {
#pragma unroll
    for (int s = 0; s < 3; s++) {
      MBARRIER_INIT(sb + GS_FULL + s * 8, 1);
      MBARRIER_INIT(sb + GS_EMPTY + s * 8, 8);
    }
  }
  __syncthreads();

#define G_BULK(c_, s_) do {                                                   \
    uint32_t fb_ = sb + GS_FULL + (s_) * 8;                                   \
    MBARRIER_EXPECT_TX(fb_, 32768u);                                          \
    uint32_t d_ = sb + (uint32_t)(s_) * GS_STAGE;                             \
    bulk_g2s(d_,             Ah + ((size_t)(mb * NCH + (c_))) * 4096, 8192u, fb_); \
    bulk_g2s(d_ + GS_TILE,   Al + ((size_t)(mb * NCH + (c_))) * 4096, 8192u, fb_); \
    bulk_g2s(d_ + 2*GS_TILE, Bh + ((size_t)(nb * NCH + (c_))) * 4096, 8192u, fb_); \
    bulk_g2s(d_ + 3*GS_TILE, Bl + ((size_t)(nb * NCH + (c_))) * 4096, 8192u, fb_); \
  } while (0)

  if (tid == 0) {
    G_BULK(0, 0);
    G_BULK(1, 1);
  }

  const int ar = lane & 15;
  const int ac = ((lane >> 4) & 1) * 8;
  const int nof = ((lane >> 4) & 1) * 8 + (lane & 7);
  const int kof2 = ((lane >> 3) & 1) * 8;

  for (int c = 0; c < NCH; c++) {
    const int cur = c % 3;
    const int cp = c + 2;
    if (cp < NCH && tid == 0) {
      const int sp = cp % 3;
      if (cp >= 3)
        MBARRIER_WAIT_PARITY(sb + GS_EMPTY + sp * 8, ((cp / 3) - 1) & 1);
      G_BULK(cp, sp);
    }
    MBARRIER_WAIT_PARITY(sb + GS_FULL + cur * 8, (c / 3) & 1);

    const uint32_t st = sb + (uint32_t)cur * GS_STAGE;
#pragma unroll
    for (int ks = 0; ks < 2; ks++) {
      const int k0 = ks * 16;
      uint32_t afh[2][4], afl[2][4];
#pragma unroll
      for (int mi = 0; mi < 2; mi++) {
        int r = wm + mi * 16 + ar;
        int seg = (k0 + ac) >> 3;
        uint32_t ad = st + (uint32_t)(r * 64 + ((seg ^ ((r >> 1) & 3)) << 4));
        ldsm4(afh[mi], ad);
        ldsm4(afl[mi], ad + GS_TILE);
      }
#pragma unroll
      for (int ni = 0; ni < 4; ni++) {
        int rb = wn + ni * 16 + nof;
        int segb = (k0 + kof2) >> 3;
        uint32_t bd = st + 2 * GS_TILE +
                      (uint32_t)(rb * 64 + ((segb ^ ((rb >> 1) & 3)) << 4));
        uint32_t bh[4], bl[4];
        ldsm4(bh, bd);
        ldsm4(bl, bd + GS_TILE);
#pragma unroll
        for (int mi = 0; mi < 2; mi++)
#pragma unroll
          for (int hh = 0; hh < 2; hh++) {
            int nj = ni * 2 + hh;
            mma16816(acc[mi][nj], afh[mi], &bh[2 * hh]);
            mma16816(acc[mi][nj], afh[mi], &bl[2 * hh]);
            mma16816(acc[mi][nj], afl[mi], &bh[2 * hh]);
          }
      }
    }
    if (lane == 0) MBARRIER_ARRIVE(sb + GS_EMPTY + cur * 8);
  }
#undef G_BULK
}

// ---------------------------------------------------------------------------
// Fused Q/K/V projection. Mode 1 (flash-Q) now emits FP16 hi/lo; mode 2
// (flash-K) emits a SINGLE fp16 value (kl dead). Mode 3 unchanged (bf16 V).
// ---------------------------------------------------------------------------
__global__ __launch_bounds__(256, 2)
void proj_fused(const __nv_bfloat16* __restrict__ qh,
                const __nv_bfloat16* __restrict__ ql,
                const __nv_bfloat16* __restrict__ kvh,
                const __nv_bfloat16* __restrict__ kvl,
                const __nv_bfloat16* __restrict__ wph,
                const __nv_bfloat16* __restrict__ wpl,
                __nv_bfloat16* __restrict__ yh,
                __nv_bfloat16* __restrict__ yl,
                __nv_bfloat16* __restrict__ kfh,
                __nv_bfloat16* __restrict__ kfl,
                __nv_bfloat16* __restrict__ vth,
                __nv_bfloat16* __restrict__ vtl) {
  extern __shared__ __align__(128) char sm[];
  const uint32_t sb = smem_u32(sm);
  const int tid = threadIdx.x, lane = tid & 31, warp = tid >> 5;
  const size_t WSZ = (size_t)D_MODEL * D_MODEL;

  int id = blockIdx.x;
  int mode, bx, by;
  const __nv_bfloat16 *Ah, *Al, *Bh, *Bl;
  __nv_bfloat16 *Ph, *Pl;
  if (id < 256) {
    mode = 1; bx = id & 7; by = id >> 3;
    Ah = qh; Al = ql; Bh = wph; Bl = wpl; Ph = yh; Pl = yl;
  } else if (id < 768) {
    mode = 2; id -= 256; bx = id & 7; by = id >> 3;
    Ah = kvh; Al = kvl; Bh = wph + WSZ; Bl = wpl + WSZ; Ph = kfh; Pl = kfl;
  } else {
    mode = 3; id -= 768; bx = id & 63; by = id >> 6;
    Ah = wph + 2 * WSZ; Al = wpl + 2 * WSZ; Bh = kvh; Bl = kvl;
    Ph = vth; Pl = vtl;
  }
  const int bm = by * 128, bn = bx * 128;

  float acc[2][8][4];
#pragma unroll
  for (int mi = 0; mi < 2; mi++)
#pragma unroll
    for (int nj = 0; nj < 8; nj++)
#pragma unroll
      for (int q = 0; q < 4; q++) acc[mi][nj][q] = 0.0f;

  gemm_mainloop(Ah, Al, Bh, Bl, by, bx, sb, tid, lane, warp, acc);

  const int wm = (warp & 3) * 32;
  const int wn = (warp >> 2) * 64;
  const int crow = lane >> 2;
  const int ccol = (lane & 3) * 2;
#pragma unroll
  for (int mi = 0; mi < 2; mi++)
#pragma unroll
    for (int nj = 0; nj < 8; nj++) {
      int m0 = bm + wm + mi * 16 + crow;
      int cc = bn + wn + nj * 8 + ccol;
#pragma unroll
      for (int half = 0; half < 2; half++) {
        int m = m0 + half * 8;
        float v0 = acc[mi][nj][half * 2], v1 = acc[mi][nj][half * 2 + 1];
        size_t t;
        if (mode == 1) {
          int b = m >> 11, q = m & 2047;
          int h = cc >> 6, dd = cc & 63;
          t = ((size_t)(b * 16 + h) * 16 + (q >> 7)) * 8192 +
              (size_t)(q & 127) * 64 + (((dd >> 3) ^ (q & 7)) << 3) + (dd & 7);
          uint32_t hi, lo;
          pack_hilo_f16(v0, v1, hi, lo);     // fp16 pair for flash-Q
          *(uint32_t*)(Ph + t) = hi;
          *(uint32_t*)(Pl + t) = lo;
        } else if (mode == 2) {
          int b = m >> 12, s = m & 4095;
          int h = cc >> 6, dd = cc & 63;
          t = ((size_t)(b * 16 + h) * 64 + (s >> 6)) * 4096 +
              (size_t)(s & 63) * 64 + (((dd >> 3) ^ (s & 7)) << 3) + (dd & 7);
          __half2 hv = __floats2half2_rn(v0, v1);  // single fp16 for flash-K
          *(uint32_t*)(Ph + t) = *reinterpret_cast<uint32_t*>(&hv);
        } else {
          int h = m >> 6, dr = m & 63;
          int b = cc >> 12, s = cc & 4095;
          t = ((size_t)(b * 16 + h) * 64 + (s >> 6)) * 4096 +
              (size_t)dr * 64 + ((((s >> 3) & 7) ^ (dr & 7)) << 3) + (s & 7);
          uint32_t hi, lo;
          pack_hilo(v0, v1, hi, lo);
          *(uint32_t*)(Ph + t) = hi;
          *(uint32_t*)(Pl + t) = lo;
        }
      }
    }
}

// ---------------------------------------------------------------------------
// Output projection (unchanged).
// ---------------------------------------------------------------------------
__global__ __launch_bounds__(256, 2)
void gemm_out(const __nv_bfloat16* __restrict__ Ah,
              const __nv_bfloat16* __restrict__ Al,
              const __nv_bfloat16* __restrict__ Bh,
              const __nv_bfloat16* __restrict__ Bl,
              float* __restrict__ C, int N) {
  extern __shared__ __align__(128) char sm[];
  const uint32_t sb = smem_u32(sm);
  const int tid = threadIdx.x, lane = tid & 31, warp = tid >> 5;
  const int bm = blockIdx.y * 128;
  const int bn = blockIdx.x * 128;

  float acc[2][8][4];
#pragma unroll
  for (int mi = 0; mi < 2; mi++)
#pragma unroll
    for (int nj = 0; nj < 8; nj++)
#pragma unroll
      for (int q = 0; q < 4; q++) acc[mi][nj][q] = 0.0f;

  gemm_mainloop(Ah, Al, Bh, Bl, blockIdx.y, blockIdx.x, sb, tid, lane, warp, acc);

  const int wm = (warp & 3) * 32;
  const int wn = (warp >> 2) * 64;
  const int crow = lane >> 2;
  const int ccol = (lane & 3) * 2;
#pragma unroll
  for (int mi = 0; mi < 2; mi++)
#pragma unroll
    for (int nj = 0; nj < 8; nj++) {
      int r0 = bm + wm + mi * 16 + crow;
      int cc = bn + wn + nj * 8 + ccol;
      *(float2*)(C + (size_t)r0 * N + cc) =
          make_float2(acc[mi][nj][0], acc[mi][nj][1]);
      *(float2*)(C + (size_t)(r0 + 8) * N + cc) =
          make_float2(acc[mi][nj][2], acc[mi][nj][3]);
    }
}

// ---------------------------------------------------------------------------
// HMMA flash attention at 2 CTAs/SM, Q parked in smem.
// NEW: QK^T in fp16 2-pass (Q = exact fp16 hi/lo pair, K = single fp16).
// KV stage = K(8KB) | Vh(8KB) | Vl(8KB) = 24KB; 2 stages; Q at 48KB..80KB.
// PV stays bf16x3.
// ---------------------------------------------------------------------------
#define FS_TILE  8192
#define FS_STAGE 24576
#define FS_QOFF  49152
#define FS_FULL  81920
#define FS_EMPTY 81936
#define FS_SMEM  82048

__global__ __launch_bounds__(256, 2)
void flash_bulk(const __nv_bfloat16* __restrict__ qfh,
                const __nv_bfloat16* __restrict__ qfl,
                const __nv_bfloat16* __restrict__ kfh,
                const __nv_bfloat16* __restrict__ vth,
                const __nv_bfloat16* __restrict__ vtl,
                const float* __restrict__ imp,
                __nv_bfloat16* __restrict__ Yh,
                __nv_bfloat16* __restrict__ Yl) {
  extern __shared__ __align__(128) char fsm[];
  const uint32_t sb = smem_u32(fsm);
  const int b = blockIdx.z, h = blockIdx.y, qb = blockIdx.x;
  const int q0 = qb * 128;
  const int tid = threadIdx.x, lane = tid & 31, warp = tid >> 5;
  const int wm = warp * 16;

  if (tid == 0) {
#pragma unroll
    for (int s = 0; s < 2; s++) {
      MBARRIER_INIT(sb + FS_FULL + s * 8, 1);
      MBARRIER_INIT(sb + FS_EMPTY + s * 8, 8);
    }
  }
  // Stage Q (persistent fp16 pair; hi at FS_QOFF, lo at +16KB).
  {
    const __nv_bfloat16* qsrc = qfh + ((size_t)(b * 16 + h) * 16 + qb) * 8192;
    const __nv_bfloat16* qsrc2 = qfl + ((size_t)(b * 16 + h) * 16 + qb) * 8192;
#pragma unroll
    for (int j = 0; j < 4; j++) {
      int idx = tid + j * 256;
      cp16(sb + FS_QOFF + idx * 16, qsrc + idx * 8);
      cp16(sb + FS_QOFF + 16384 + idx * 16, qsrc2 + idx * 8);
    }
  }
  CP_COMMIT();
  __syncthreads();              // mbar init visible

  const __nv_bfloat16* Kb = kfh + ((size_t)(b * 16 + h) * 64) * 4096;
  const __nv_bfloat16* Vb = vth + ((size_t)(b * 16 + h) * 64) * 4096;
  const __nv_bfloat16* Vb2 = vtl + ((size_t)(b * 16 + h) * 64) * 4096;

#define F_BULK(t_, s_) do {                                                   \
    uint32_t fb_ = sb + FS_FULL + (s_) * 8;                                   \
    MBARRIER_EXPECT_TX(fb_, 24576u);                                          \
    uint32_t d_ = sb + (uint32_t)(s_) * FS_STAGE;                             \
    bulk_g2s(d_,             Kb  + (size_t)(t_) * 4096, 8192u, fb_);          \
    bulk_g2s(d_ + FS_TILE,   Vb  + (size_t)(t_) * 4096, 8192u, fb_);          \
    bulk_g2s(d_ + 2*FS_TILE, Vb2 + (size_t)(t_) * 4096, 8192u, fb_);          \
  } while (0)

  if (tid == 0) {
    F_BULK(0, 0);               // only stage 0; loop fills stage 1 at t=0
  }

  const int ar = lane & 15;
  const int ac = ((lane >> 4) & 1) * 8;
  const int nof = ((lane >> 4) & 1) * 8 + (lane & 7);
  const int kof2 = ((lane >> 3) & 1) * 8;

  asm volatile("cp.async.wait_group 0;");
  __syncthreads();              // Q visible to all warps

  const int q2 = (lane & 3) * 2;
  float lg[4];
  lg[0] = logf(fmaxf(imp[b * NHEADS + (q2 & 15)], 1e-6f));
  lg[1] = logf(fmaxf(imp[b * NHEADS + ((q2 + 1) & 15)], 1e-6f));
  lg[2] = logf(fmaxf(imp[b * NHEADS + ((q2 + 8) & 15)], 1e-6f));
  lg[3] = logf(fmaxf(imp[b * NHEADS + ((q2 + 9) & 15)], 1e-6f));

  float m0 = -INFINITY, m1 = -INFINITY, l0 = 0.0f, l1 = 0.0f;
  float y[8][4];
#pragma unroll
  for (int nf = 0; nf < 8; nf++)
#pragma unroll
    for (int q = 0; q < 4; q++) y[nf][q] = 0.0f;

  const int NT = SKV / 64;
  for (int t = 0; t < NT; t++) {
    const int cur = t & 1;
    const int cp = t + 1;
    if (cp < NT && tid == 0) {
      const int sp = cp & 1;
      if (cp >= 2)
        MBARRIER_WAIT_PARITY(sb + FS_EMPTY + sp * 8, ((cp >> 1) - 1) & 1);
      F_BULK(cp, sp);
    }
    MBARRIER_WAIT_PARITY(sb + FS_FULL + cur * 8, (t >> 1) & 1);
    const uint32_t st = sb + (uint32_t)cur * FS_STAGE;

    // ---- S = Q K^T (fp16 2-pass: (qh+ql) x k16) ----
    float s[8][4];
#pragma unroll
    for (int nf = 0; nf < 8; nf++)
#pragma unroll
      for (int q = 0; q < 4; q++) s[nf][q] = 0.0f;
#pragma unroll
    for (int kc = 0; kc < 4; kc++) {
      uint32_t qa[4], qlo[4];
      {
        int r = wm + ar;
        int seg = 2 * kc + (ac >> 3);
        uint32_t ad = sb + FS_QOFF +
                      (uint32_t)(r * 128 + ((seg ^ (r & 7)) << 4));
        ldsm4(qa, ad);
        ldsm4(qlo, ad + 16384);
      }
#pragma unroll
      for (int n2 = 0; n2 < 4; n2++) {
        int r = n2 * 16 + nof;
        int seg = 2 * kc + (kof2 >> 3);
        uint32_t bd = st + (uint32_t)(r * 128 + ((seg ^ (r & 7)) << 4));
        uint32_t kh[4];
        ldsm4(kh, bd);
#pragma unroll
        for (int hh = 0; hh < 2; hh++) {
          mma16816_f16(s[n2 * 2 + hh], qa, &kh[2 * hh]);
          mma16816_f16(s[n2 * 2 + hh], qlo, &kh[2 * hh]);
        }
      }
    }

    float mt0 = -INFINITY, mt1 = -INFINITY;
#pragma unroll
    for (int nf = 0; nf < 8; nf++) {
      const int p = (nf & 1) * 2;
      s[nf][0] = s[nf][0] * 0.125f + lg[p];
      s[nf][1] = s[nf][1] * 0.125f + lg[p + 1];
      s[nf][2] = s[nf][2] * 0.125f + lg[p];
      s[nf][3] = s[nf][3] * 0.125f + lg[p + 1];
      mt0 = fmaxf(mt0, fmaxf(s[nf][0], s[nf][1]));
      mt1 = fmaxf(mt1, fmaxf(s[nf][2], s[nf][3]));
    }
    mt0 = fmaxf(mt0, __shfl_xor_sync(0xffffffffu, mt0, 1));
    mt0 = fmaxf(mt0, __shfl_xor_sync(0xffffffffu, mt0, 2));
    mt1 = fmaxf(mt1, __shfl_xor_sync(0xffffffffu, mt1, 1));
    mt1 = fmaxf(mt1, __shfl_xor_sync(0xffffffffu, mt1, 2));

    float mn0 = fmaxf(m0, mt0), mn1 = fmaxf(m1, mt1);
    float c0 = __expf(m0 - mn0), c1 = __expf(m1 - mn1);
    m0 = mn0; m1 = mn1;

    uint32_t ph[4][4], pl[4][4];
    float r0 = 0.0f, r1 = 0.0f;
#pragma unroll
    for (int nf = 0; nf < 8; nf++) {
      float p0 = __expf(s[nf][0] - m0);
      float p1 = __expf(s[nf][1] - m0);
      float p2 = __expf(s[nf][2] - m1);
      float p3 = __expf(s[nf][3] - m1);
      r0 += p0 + p1;
      r1 += p2 + p3;
      const int kc = nf >> 1, o = (nf & 1) * 2;
      pack_hilo(p0, p1, ph[kc][o], pl[kc][o]);
      pack_hilo(p2, p3, ph[kc][o + 1], pl[kc][o + 1]);
    }
    r0 += __shfl_xor_sync(0xffffffffu, r0, 1);
    r0 += __shfl_xor_sync(0xffffffffu, r0, 2);
    r1 += __shfl_xor_sync(0xffffffffu, r1, 1);
    r1 += __shfl_xor_sync(0xffffffffu, r1, 2);
    l0 = l0 * c0 + r0;
    l1 = l1 * c1 + r1;
#pragma unroll
    for (int nf = 0; nf < 8; nf++) {
      y[nf][0] *= c0; y[nf][1] *= c0;
      y[nf][2] *= c1; y[nf][3] *= c1;
    }

    // ---- y += P V (bf16x3) ----
#pragma unroll
    for (int kc = 0; kc < 4; kc++) {
#pragma unroll
      for (int n2 = 0; n2 < 4; n2++) {
        int r = n2 * 16 + nof;
        int seg = 2 * kc + (kof2 >> 3);
        uint32_t bd = st + FS_TILE +
                      (uint32_t)(r * 128 + ((seg ^ (r & 7)) << 4));
        uint32_t vh[4], vl[4];
        ldsm4(vh, bd);
        ldsm4(vl, bd + FS_TILE);
#pragma unroll
        for (int hh = 0; hh < 2; hh++) {
          mma16816(y[n2 * 2 + hh], ph[kc], &vh[2 * hh]);
          mma16816(y[n2 * 2 + hh], ph[kc], &vl[2 * hh]);
          mma16816(y[n2 * 2 + hh], pl[kc], &vh[2 * hh]);
        }
      }
    }
    if (lane == 0) MBARRIER_ARRIVE(sb + FS_EMPTY + cur * 8);
  }

  const float i0 = 1.0f / l0, i1 = 1.0f / l1;
  const int row0 = q0 + wm + (lane >> 2);
#pragma unroll
  for (int nf = 0; nf < 8; nf++) {
    int k = h * HDIM + 8 * nf + q2;
    int kc = k >> 5, seg0 = (k >> 3) & 3, klow = k & 7;
#pragma unroll
    for (int half = 0; half < 2; half++) {
      int m = b * TQ + row0 + half * 8;
      float v0 = y[nf][half * 2] * (half ? i1 : i0);
      float v1 = y[nf][half * 2 + 1] * (half ? i1 : i0);
      int r = m & 127, mb2 = m >> 7;
      size_t t = ((size_t)mb2 * 32 + kc) * 4096 + (size_t)r * 32 +
                 ((seg0 ^ ((r >> 1) & 3)) << 3) + klow;
      uint32_t hi, lo;
      pack_hilo(v0, v1, hi, lo);
      *(uint32_t*)(Yh + t) = hi;
      *(uint32_t*)(Yl + t) = lo;
    }
  }
}

// ---------------------------------------------------------------------------
extern "C" void kernel_launch(void* const* d_in, const int* in_sizes, int n_in,
                              void* d_out, int out_size) {
  const float* query     = (const float*)d_in[0];
  const float* key_value = (const float*)d_in[1];
  const float* imp       = (const float*)d_in[2];
  const float* Wq        = (const float*)d_in[3];
  const float* Wk        = (const float*)d_in[4];
  const float* Wv        = (const float*)d_in[5];
  const float* Wo        = (const float*)d_in[6];
  float* out = (float*)d_out;

  __nv_bfloat16 *qh, *ql, *kvh, *kvl, *yh, *yl, *wh, *wl, *kfh, *kfl, *vth, *vtl;
  cudaGetSymbolAddress((void**)&qh, g_qh);
  cudaGetSymbolAddress((void**)&ql, g_ql);
  cudaGetSymbolAddress((void**)&kvh, g_kvh);
  cudaGetSymbolAddress((void**)&kvl, g_kvl);
  cudaGetSymbolAddress((void**)&yh, g_yh);
  cudaGetSymbolAddress((void**)&yl, g_yl);
  cudaGetSymbolAddress((void**)&wh, g_wh);
  cudaGetSymbolAddress((void**)&wl, g_wl);
  cudaGetSymbolAddress((void**)&kfh, g_kfh);
  cudaGetSymbolAddress((void**)&kfl, g_kfl);
  cudaGetSymbolAddress((void**)&vth, g_vth);
  cudaGetSymbolAddress((void**)&vtl, g_vtl);
  const size_t WSZ = (size_t)D_MODEL * D_MODEL;

  cudaFuncSetAttribute(proj_fused,
                       cudaFuncAttributeMaxDynamicSharedMemorySize, GS_SMEM);
  cudaFuncSetAttribute(gemm_out,
                       cudaFuncAttributeMaxDynamicSharedMemorySize, GS_SMEM);
  cudaFuncSetAttribute(flash_bulk,
                       cudaFuncAttributeMaxDynamicSharedMemorySize, FS_SMEM);

  pack_all4<<<PSTRIDE / 256, 256>>>(query, key_value, Wq, Wk, Wv, Wo,
                                    qh, ql, kvh, kvl, wh, wl);

  proj_fused<<<1280, 256, GS_SMEM>>>(qh, ql, kvh, kvl, wh, wl,
                                     yh, yl, kfh, kfl, vth, vtl);

  flash_bulk<<<dim3(TQ / 128, NHEADS, BATCH), 256, FS_SMEM>>>(
      yh, yl, kfh, vth, vtl, imp, qh, ql);

  gemm_out<<<dim3(8, 32), 256, GS_SMEM>>>(
      qh, ql, wh + 3 * WSZ, wl + 3 * WSZ, out, D_MODEL);
}